// round 9
// baseline (speedup 1.0000x reference)
#include <cuda_runtime.h>
#include <cuda_fp16.h>
#include <cstdint>

#define NN 100000
#define EE 1200000

// ---------------- device scratch (static, allocation-free) ----------------
__device__ int   g_cnt[2 * NN];
__device__ int   g_rp_pos[NN + 1];
__device__ int   g_rp_neg[NN + 1];
__device__ int   g_cur_pos[NN];
__device__ int   g_cur_neg[NN];
__device__ float g_inv_pos[NN];
__device__ float g_inv_neg[NN];
__device__ int   g_src_pos[EE];
__device__ int   g_src_neg[EE];
__device__ int   g_bsum_pos[128];
__device__ int   g_bsum_neg[128];
__device__ __align__(16) __half g_U0h[NN * 128];  // [yp(64) | yn(64)] fp16 (gathered by layer0)
__device__ float g_U0s[NN * 128];                  // [sp(64) | sn(64)] fp32 (self terms)
__device__ __align__(16) __half g_Zh[NN * 128];   // z after layer 0 (fp16)
__device__ __align__(16) __half g_Z2h[NN * 128];  // z after layer 1 (fp16)
__device__ float g_AGGP[NN * 128];  // [Apos[0:64] | Aneg[64:128]]
__device__ float g_AGGN[NN * 128];  // [Apos[64:128] | Aneg[0:64]]

// packed bf16 weights: 4 layer stacks (24576 B each) then gemm0 (2 x 32768 B) = 163840 B
__device__ __align__(16) uint32_t g_WB_h[40960];
__device__ __align__(16) uint32_t g_WB_l[40960];

// ---------------- helpers ----------------
__device__ __forceinline__ uint32_t smem_u32(const void* p) {
    uint32_t a;
    asm("{ .reg .u64 t; cvta.to.shared.u64 t, %1; cvt.u32.u64 %0, t; }" : "=r"(a) : "l"(p));
    return a;
}
__device__ __forceinline__ uint32_t swz(uint32_t o) { return o ^ ((o >> 3) & 0x70); }

__device__ __forceinline__ void split_pair(float2 v, uint32_t& h2, uint32_t& l2) {
    asm("cvt.rn.bf16x2.f32 %0, %1, %2;" : "=r"(h2) : "f"(v.y), "f"(v.x));
    float lx = v.x - __uint_as_float(h2 << 16);
    float ly = v.y - __uint_as_float(h2 & 0xffff0000u);
    asm("cvt.rn.bf16x2.f32 %0, %1, %2;" : "=r"(l2) : "f"(ly), "f"(lx));
}

__device__ __forceinline__ void ldsm4(uint32_t* r, uint32_t addr) {
    asm volatile("ldmatrix.sync.aligned.m8n8.x4.shared.b16 {%0,%1,%2,%3}, [%4];"
                 : "=r"(r[0]), "=r"(r[1]), "=r"(r[2]), "=r"(r[3]) : "r"(addr));
}

__device__ __forceinline__ void mma16816(float* c, const uint32_t* a, const uint32_t* b) {
    asm volatile(
        "mma.sync.aligned.m16n8k16.row.col.f32.bf16.bf16.f32 "
        "{%0,%1,%2,%3}, {%4,%5,%6,%7}, {%8,%9}, {%0,%1,%2,%3};"
        : "+f"(c[0]), "+f"(c[1]), "+f"(c[2]), "+f"(c[3])
        : "r"(a[0]), "r"(a[1]), "r"(a[2]), "r"(a[3]), "r"(b[0]), "r"(b[1]));
}

__device__ __forceinline__ void acc_h4(float4& a, uint2 raw) {
    float2 f0 = __half22float2(*(const __half2*)&raw.x);
    float2 f1 = __half22float2(*(const __half2*)&raw.y);
    a.x += f0.x; a.y += f0.y; a.z += f1.x; a.w += f1.y;
}

// ---------------- CSR build ----------------
__global__ void zero_cnt_k() {
    int i = blockIdx.x * blockDim.x + threadIdx.x;
    if (i < 2 * NN) g_cnt[i] = 0;
}
__global__ void hist_k(const int* __restrict__ dst, int which) {
    int* cnt = g_cnt + which * NN;
    for (int i = blockIdx.x * blockDim.x + threadIdx.x; i < EE; i += gridDim.x * blockDim.x)
        atomicAdd(&cnt[dst[i]], 1);
}
__global__ void scan1_k(int which) {
    const int* cnt = g_cnt + which * NN;
    int* incl = which ? g_rp_neg : g_rp_pos;
    int* bsum = which ? g_bsum_neg : g_bsum_pos;
    __shared__ int sh[1024];
    int i = blockIdx.x * 1024 + threadIdx.x;
    int v = (i < NN) ? cnt[i] : 0;
    sh[threadIdx.x] = v;
    __syncthreads();
    for (int off = 1; off < 1024; off <<= 1) {
        int t = (threadIdx.x >= off) ? sh[threadIdx.x - off] : 0;
        __syncthreads();
        sh[threadIdx.x] += t;
        __syncthreads();
    }
    if (i < NN) incl[i] = sh[threadIdx.x];
    if (threadIdx.x == 1023) bsum[blockIdx.x] = sh[1023];
}
__global__ void scan2_k(int nb, int which) {
    int* bsum = which ? g_bsum_neg : g_bsum_pos;
    __shared__ int sh[128];
    int v = (threadIdx.x < nb) ? bsum[threadIdx.x] : 0;
    sh[threadIdx.x] = v;
    __syncthreads();
    for (int off = 1; off < 128; off <<= 1) {
        int t = (threadIdx.x >= off) ? sh[threadIdx.x - off] : 0;
        __syncthreads();
        sh[threadIdx.x] += t;
        __syncthreads();
    }
    if (threadIdx.x < nb) bsum[threadIdx.x] = sh[threadIdx.x] - v;
}
__global__ void scan3_k(int which) {
    const int* cnt = g_cnt + which * NN;
    int* rp = which ? g_rp_neg : g_rp_pos;
    int* cur = which ? g_cur_neg : g_cur_pos;
    float* inv = which ? g_inv_neg : g_inv_pos;
    const int* bsum = which ? g_bsum_neg : g_bsum_pos;
    int i = blockIdx.x * blockDim.x + threadIdx.x;
    if (i < NN) {
        int inc = rp[i] + bsum[i >> 10];
        int c = cnt[i];
        int ex = inc - c;
        rp[i] = ex;
        cur[i] = ex;
        inv[i] = 1.0f / (float)(c > 0 ? c : 1);
    }
    if (i == 0) rp[NN] = EE;
}
__global__ void scatter_k(const int* __restrict__ src, const int* __restrict__ dst, int which) {
    int* cur = which ? g_cur_neg : g_cur_pos;
    int* out = which ? g_src_neg : g_src_pos;
    for (int i = blockIdx.x * blockDim.x + threadIdx.x; i < EE; i += gridDim.x * blockDim.x) {
        int d = dst[i];
        int p = atomicAdd(&cur[d], 1);
        out[p] = src[i];
    }
}

// ---------------- weight prep: fp32 -> bf16 hi/lo, [n][k] rows, SW128-swizzled 64-k chunks ----------------
__global__ void prep_w_k(const float* __restrict__ Wl_pos, const float* __restrict__ Wr_pos,
                         const float* __restrict__ Wl_neg, const float* __restrict__ Wr_neg,
                         const float* __restrict__ Wp_l, const float* __restrict__ Wn_l,
                         const float* __restrict__ Wp_r, const float* __restrict__ Wn_r) {
    int idx = blockIdx.x * blockDim.x + threadIdx.x;
    float2 v;
    uint32_t off;
    if (idx < 24576) {
        int stack = idx / 6144, rem = idx % 6144;
        int n = rem / 96, kp = rem % 96, k = kp * 2;
        int l = stack >> 1, h = stack & 1;
        const float* WL = h ? Wl_neg : Wl_pos;  // [2][128][64]
        const float* WR = h ? Wr_neg : Wr_pos;  // [2][64][64]
        if (k < 128) {
            v.x = WL[l * 8192 + k * 64 + n];
            v.y = WL[l * 8192 + (k + 1) * 64 + n];
        } else {
            int kk = k - 128;
            v.x = WR[l * 4096 + kk * 64 + n];
            v.y = WR[l * 4096 + (kk + 1) * 64 + n];
        }
        off = (uint32_t)stack * 24576u + (uint32_t)(k >> 6) * 8192u + swz((uint32_t)n * 128u + (k & 63) * 2u);
    } else if (idx < 24576 + 16384) {
        int j = idx - 24576;
        int colsel = j / 8192, rem = j % 8192;
        int n = rem / 64, kp = rem % 64, k = kp * 2;
        const float* W = (n < 64) ? (colsel ? Wp_r : Wp_l) : (colsel ? Wn_r : Wn_l);
        int nn = n & 63;
        v.x = W[k * 64 + nn];
        v.y = W[(k + 1) * 64 + nn];
        off = 98304u + (uint32_t)colsel * 32768u + (uint32_t)(k >> 6) * 16384u + swz((uint32_t)n * 128u + (k & 63) * 2u);
    } else {
        return;
    }
    uint32_t h2, l2;
    split_pair(v, h2, l2);
    g_WB_h[off >> 2] = h2;
    g_WB_l[off >> 2] = l2;
}

// ---------------- unified HMMA GEMM ----------------
__global__ void __launch_bounds__(256) mma_gemm_k(
    const float* __restrict__ A0, const __half* __restrict__ A1h, int zOff, int nkc,
    int bBase, int bStride,
    float* __restrict__ outF, __half* __restrict__ outH, int outOff,
    const float* __restrict__ bias, int act, int outHalf)
{
    __shared__ uint32_t sAh[4096], sAl[4096];
    __shared__ uint32_t sBh[2048], sBl[2048];
    int tid = threadIdx.x, wid = tid >> 5, lane = tid & 31;
    int v0 = blockIdx.x * 128;

    uint32_t aHb = smem_u32(sAh), aLb = smem_u32(sAl);
    uint32_t bHb = smem_u32(sBh), bLb = smem_u32(sBl);

    int lr = lane & 7, g = lane >> 3;
    int arow = wid * 16 + lr + (g & 1) * 8;
    uint32_t aPreH = aHb + arow * 128, aPreL = aLb + arow * 128;
    uint32_t xmA = (uint32_t)(arow & 7) * 16;
    uint32_t kbA = (uint32_t)(g >> 1) * 16;
    int brow = lr + (g >> 1) * 8;
    uint32_t xmB = (uint32_t)lr * 16;
    uint32_t kbB = (uint32_t)(g & 1) * 16;

    float acc[8][4] = {};

    for (int kc = 0; kc < nkc; kc++) {
        {
            const uint4* bh = (const uint4*)((const char*)g_WB_h + bBase + kc * bStride);
            const uint4* bl = (const uint4*)((const char*)g_WB_l + bBase + kc * bStride);
            for (int i = tid; i < 512; i += 256) {
                ((uint4*)sBh)[i] = bh[i];
                ((uint4*)sBl)[i] = bl[i];
            }
        }
        for (int idx = tid; idx < 4096; idx += 256) {
            int r = idx >> 5, kp = idx & 31;
            float2 v = make_float2(0.f, 0.f);
            if (v0 + r < NN) {
                if (kc == 2)
                    v = __half22float2(*(const __half2*)(A1h + (size_t)(v0 + r) * 128 + zOff + kp * 2));
                else
                    v = *(const float2*)(A0 + (size_t)(v0 + r) * 128 + kc * 64 + kp * 2);
            }
            uint32_t h2, l2;
            split_pair(v, h2, l2);
            uint32_t o = swz((uint32_t)r * 128u + (uint32_t)kp * 4u);
            *(uint32_t*)((char*)sAh + o) = h2;
            *(uint32_t*)((char*)sAl + o) = l2;
        }
        __syncthreads();

#pragma unroll
        for (int ks = 0; ks < 4; ks++) {
            uint32_t kb = ks * 32;
            uint32_t ah[4], al[4];
            ldsm4(ah, aPreH + ((kb + kbA) ^ xmA));
            ldsm4(al, aPreL + ((kb + kbA) ^ xmA));
#pragma unroll
            for (int nt2 = 0; nt2 < 4; nt2++) {
                int n = nt2 * 16 + brow;
                uint32_t bo = (uint32_t)n * 128 + ((kb + kbB) ^ xmB);
                uint32_t bh4[4], bl4[4];
                ldsm4(bh4, bHb + bo);
                ldsm4(bl4, bLb + bo);
                mma16816(acc[nt2 * 2],     ah, bh4);
                mma16816(acc[nt2 * 2 + 1], ah, bh4 + 2);
                mma16816(acc[nt2 * 2],     al, bh4);
                mma16816(acc[nt2 * 2 + 1], al, bh4 + 2);
                mma16816(acc[nt2 * 2],     ah, bl4);
                mma16816(acc[nt2 * 2 + 1], ah, bl4 + 2);
            }
        }
        __syncthreads();
    }

    int r0 = v0 + wid * 16 + (lane >> 2);
    int cb = (lane & 3) * 2;
#pragma unroll
    for (int j = 0; j < 8; j++) {
        int col = j * 8 + cb;
        float bx = 0.f, by = 0.f;
        if (bias) { bx = bias[col]; by = bias[col + 1]; }
        float ox = acc[j][0] + bx, oy = acc[j][1] + by;
        float px = acc[j][2] + bx, py = acc[j][3] + by;
        if (act) { ox = tanhf(ox); oy = tanhf(oy); px = tanhf(px); py = tanhf(py); }
        if (outHalf) {
            if (r0 < NN)     *(__half2*)(outH + (size_t)r0 * 128 + outOff + col)       = __floats2half2_rn(ox, oy);
            if (r0 + 8 < NN) *(__half2*)(outH + (size_t)(r0 + 8) * 128 + outOff + col) = __floats2half2_rn(px, py);
        } else {
            if (r0 < NN)     *(float2*)(outF + (size_t)r0 * 128 + outOff + col)       = make_float2(ox, oy);
            if (r0 + 8 < NN) *(float2*)(outF + (size_t)(r0 + 8) * 128 + outOff + col) = make_float2(px, py);
        }
    }
}

// ---------------- Layer 0: warp-per-node fp16 mean-gather, interleaved pos/neg chains ----------------
__global__ void layer0_k(const float* __restrict__ bp, const float* __restrict__ bn) {
    int v = (blockIdx.x * blockDim.x + threadIdx.x) >> 5;
    int lane = threadIdx.x & 31;
    if (v >= NN) return;
    int c2 = lane * 2;
    float2 aP0 = make_float2(0.f, 0.f), aP1 = make_float2(0.f, 0.f);
    float2 aN0 = make_float2(0.f, 0.f), aN1 = make_float2(0.f, 0.f);
    int i = g_rp_pos[v], ep = g_rp_pos[v + 1];
    int j = g_rp_neg[v], en = g_rp_neg[v + 1];
    const __half* ZP = g_U0h;        // pos gathers read cols [0,64)
    const __half* ZN = g_U0h + 64;   // neg gathers read cols [64,128)
    while (i + 2 <= ep && j + 2 <= en) {
        int s0 = g_src_pos[i], s1 = g_src_pos[i + 1];
        int t0 = g_src_neg[j], t1 = g_src_neg[j + 1];
        float2 p0 = __half22float2(*(const __half2*)(ZP + (size_t)s0 * 128 + c2));
        float2 p1 = __half22float2(*(const __half2*)(ZP + (size_t)s1 * 128 + c2));
        float2 q0 = __half22float2(*(const __half2*)(ZN + (size_t)t0 * 128 + c2));
        float2 q1 = __half22float2(*(const __half2*)(ZN + (size_t)t1 * 128 + c2));
        aP0.x += p0.x; aP0.y += p0.y; aP1.x += p1.x; aP1.y += p1.y;
        aN0.x += q0.x; aN0.y += q0.y; aN1.x += q1.x; aN1.y += q1.y;
        i += 2; j += 2;
    }
    for (; i < ep; i++) {
        int s = g_src_pos[i];
        float2 p = __half22float2(*(const __half2*)(ZP + (size_t)s * 128 + c2));
        aP0.x += p.x; aP0.y += p.y;
    }
    for (; j < en; j++) {
        int t = g_src_neg[j];
        float2 q = __half22float2(*(const __half2*)(ZN + (size_t)t * 128 + c2));
        aN0.x += q.x; aN0.y += q.y;
    }
    float ax = aP0.x + aP1.x, ay = aP0.y + aP1.y;
    float nx = aN0.x + aN1.x, ny = aN0.y + aN1.y;
    float ipv = g_inv_pos[v], inv = g_inv_neg[v];
    float2 sp = *(const float2*)(g_U0s + (size_t)v * 128 + c2);
    float2 sn = *(const float2*)(g_U0s + (size_t)v * 128 + 64 + c2);
    float2 b1 = *(const float2*)(bp + c2);
    float2 b2 = *(const float2*)(bn + c2);
    float zpx = tanhf(ax * ipv + sp.x + b1.x), zpy = tanhf(ay * ipv + sp.y + b1.y);
    float znx = tanhf(nx * inv + sn.x + b2.x), zny = tanhf(ny * inv + sn.y + b2.y);
    *(__half2*)(g_Zh + (size_t)v * 128 + c2) = __floats2half2_rn(zpx, zpy);
    *(__half2*)(g_Zh + (size_t)v * 128 + 64 + c2) = __floats2half2_rn(znx, zny);
}

// ---------------- Layer aggregation: warp-per-node, interleaved pos/neg chains ----------------
__global__ void agg_k(int zsel) {
    const __half* Z = zsel ? g_Z2h : g_Zh;
    int v = (blockIdx.x * blockDim.x + threadIdx.x) >> 5;
    int lane = threadIdx.x & 31;
    if (v >= NN) return;
    int c4 = lane * 4;
    float4 aP0 = make_float4(0.f, 0.f, 0.f, 0.f), aP1 = make_float4(0.f, 0.f, 0.f, 0.f);
    float4 aN0 = make_float4(0.f, 0.f, 0.f, 0.f), aN1 = make_float4(0.f, 0.f, 0.f, 0.f);
    int i = g_rp_pos[v], ep = g_rp_pos[v + 1];
    int j = g_rp_neg[v], en = g_rp_neg[v + 1];
    while (i + 2 <= ep && j + 2 <= en) {
        int s0 = g_src_pos[i], s1 = g_src_pos[i + 1];
        int t0 = g_src_neg[j], t1 = g_src_neg[j + 1];
        uint2 r0 = *(const uint2*)(Z + (size_t)s0 * 128 + c4);
        uint2 r1 = *(const uint2*)(Z + (size_t)s1 * 128 + c4);
        uint2 u0 = *(const uint2*)(Z + (size_t)t0 * 128 + c4);
        uint2 u1 = *(const uint2*)(Z + (size_t)t1 * 128 + c4);
        acc_h4(aP0, r0); acc_h4(aP1, r1);
        acc_h4(aN0, u0); acc_h4(aN1, u1);
        i += 2; j += 2;
    }
    for (; i < ep; i++) {
        int s = g_src_pos[i];
        acc_h4(aP0, *(const uint2*)(Z + (size_t)s * 128 + c4));
    }
    for (; j < en; j++) {
        int t = g_src_neg[j];
        acc_h4(aN0, *(const uint2*)(Z + (size_t)t * 128 + c4));
    }
    float4 aP = make_float4(aP0.x + aP1.x, aP0.y + aP1.y, aP0.z + aP1.z, aP0.w + aP1.w);
    float4 aN = make_float4(aN0.x + aN1.x, aN0.y + aN1.y, aN0.z + aN1.z, aN0.w + aN1.w);
    float ipv = g_inv_pos[v], inv = g_inv_neg[v];
    aP.x *= ipv; aP.y *= ipv; aP.z *= ipv; aP.w *= ipv;
    aN.x *= inv; aN.y *= inv; aN.z *= inv; aN.w *= inv;
    if (lane < 16) {
        *(float4*)(g_AGGP + (size_t)v * 128 + c4) = aP;
        *(float4*)(g_AGGN + (size_t)v * 128 + 64 + c4) = aN;
    } else {
        *(float4*)(g_AGGP + (size_t)v * 128 + c4) = aN;
        *(float4*)(g_AGGN + (size_t)v * 128 + c4 - 64) = aP;
    }
}

// ---------------- host launcher (single stream, capture-safe) ----------------
extern "C" void kernel_launch(void* const* d_in, const int* in_sizes, int n_in,
                              void* d_out, int out_size) {
    const float* x = (const float*)d_in[0];
    const int* pe = (const int*)d_in[1];   // int32 (JAX x64 disabled)
    const int* ne = (const int*)d_in[2];
    const float* Wp_l = (const float*)d_in[3];
    const float* Wp_r = (const float*)d_in[4];
    const float* bp = (const float*)d_in[5];
    const float* Wn_l = (const float*)d_in[6];
    const float* Wn_r = (const float*)d_in[7];
    const float* bn = (const float*)d_in[8];
    const float* Wl_pos = (const float*)d_in[9];
    const float* Wr_pos = (const float*)d_in[10];
    const float* b_pos = (const float*)d_in[11];
    const float* Wl_neg = (const float*)d_in[12];
    const float* Wr_neg = (const float*)d_in[13];
    const float* b_neg = (const float*)d_in[14];
    float* out = (float*)d_out;

    float *dU0s, *dAGGP, *dAGGN;
    __half *dU0h, *dZh, *dZ2h;
    cudaGetSymbolAddress((void**)&dU0h, g_U0h);
    cudaGetSymbolAddress((void**)&dU0s, g_U0s);
    cudaGetSymbolAddress((void**)&dZh, g_Zh);
    cudaGetSymbolAddress((void**)&dZ2h, g_Z2h);
    cudaGetSymbolAddress((void**)&dAGGP, g_AGGP);
    cudaGetSymbolAddress((void**)&dAGGN, g_AGGN);

    // --- weight prep ---
    prep_w_k<<<160, 256>>>(Wl_pos, Wr_pos, Wl_neg, Wr_neg, Wp_l, Wn_l, Wp_r, Wn_r);

    // --- CSR build (single stream) ---
    zero_cnt_k<<<(2 * NN + 255) / 256, 256>>>();
    hist_k<<<1024, 256>>>(pe + EE, 0);
    hist_k<<<1024, 256>>>(ne + EE, 1);
    const int NB = (NN + 1023) / 1024;
    scan1_k<<<NB, 1024>>>(0);
    scan2_k<<<1, 128>>>(NB, 0);
    scan3_k<<<(NN + 255) / 256, 256>>>(0);
    scatter_k<<<1024, 256>>>(pe, pe + EE, 0);
    scan1_k<<<NB, 1024>>>(1);
    scan2_k<<<1, 128>>>(NB, 1);
    scan3_k<<<(NN + 255) / 256, 256>>>(1);
    scatter_k<<<1024, 256>>>(ne, ne + EE, 1);

    const int NBT = (NN + 127) / 128;  // 782

    // --- layer 0 pre-GEMMs ---
    for (int h = 0; h < 2; h++) {
        mma_gemm_k<<<NBT, 256>>>(x, nullptr, 0, 2, 98304 + 0 * 32768 + h * 8192, 16384,
                                 nullptr, dU0h, h * 64, nullptr, 0, 1);
        mma_gemm_k<<<NBT, 256>>>(x, nullptr, 0, 2, 98304 + 1 * 32768 + h * 8192, 16384,
                                 dU0s, nullptr, h * 64, nullptr, 0, 0);
    }
    const int NBW = (NN * 32 + 255) / 256;
    layer0_k<<<NBW, 256>>>(bp, bn);

    // --- layer 1 ---
    agg_k<<<NBW, 256>>>(0);
    mma_gemm_k<<<NBT, 256>>>(dAGGP, dZh, 0, 3, 0 * 24576, 8192, nullptr, dZ2h, 0, b_pos, 1, 1);
    mma_gemm_k<<<NBT, 256>>>(dAGGN, dZh, 64, 3, 1 * 24576, 8192, nullptr, dZ2h, 64, b_neg, 1, 1);

    // --- layer 2 ---
    agg_k<<<NBW, 256>>>(1);
    mma_gemm_k<<<NBT, 256>>>(dAGGP, dZ2h, 0, 3, 2 * 24576, 8192, out, nullptr, 0, b_pos + 64, 1, 0);
    mma_gemm_k<<<NBT, 256>>>(dAGGN, dZ2h, 64, 3, 3 * 24576, 8192, out, nullptr, 64, b_neg + 64, 1, 0);
}

// round 10
// speedup vs baseline: 1.4203x; 1.4203x over previous
#include <cuda_runtime.h>
#include <cuda_fp16.h>
#include <cstdint>

#define NN 100000
#define EE 1200000

// ---------------- device scratch (static, allocation-free) ----------------
__device__ int   g_cnt[2 * NN];
__device__ int   g_rp_pos[NN + 1];
__device__ int   g_rp_neg[NN + 1];
__device__ int   g_cur_pos[NN];
__device__ int   g_cur_neg[NN];
__device__ float g_inv_pos[NN];
__device__ float g_inv_neg[NN];
__device__ int   g_src_pos[EE];
__device__ int   g_src_neg[EE];
__device__ int   g_bsum_pos[128];
__device__ int   g_bsum_neg[128];
__device__ __align__(16) __half g_U0h[NN * 128];  // [yp(64) | yn(64)] fp16 (gathered by layer0)
__device__ float g_U0s[NN * 128];                  // [sp(64) | sn(64)] fp32 (self terms)
__device__ __align__(16) __half g_Zh[NN * 128];   // z after layer 0 (fp16)
__device__ __align__(16) __half g_Z2h[NN * 128];  // z after layer 1 (fp16)
__device__ float g_AGGP[NN * 128];  // [Apos[0:64] | Aneg[64:128]]
__device__ float g_AGGN[NN * 128];  // [Apos[64:128] | Aneg[0:64]]

// packed bf16 weights: 4 layer stacks (24576 B each) then gemm0 (2 x 32768 B) = 163840 B
__device__ __align__(16) uint32_t g_WB_h[40960];
__device__ __align__(16) uint32_t g_WB_l[40960];

// ---------------- helpers ----------------
__device__ __forceinline__ uint32_t smem_u32(const void* p) {
    uint32_t a;
    asm("{ .reg .u64 t; cvta.to.shared.u64 t, %1; cvt.u32.u64 %0, t; }" : "=r"(a) : "l"(p));
    return a;
}
__device__ __forceinline__ uint32_t swz(uint32_t o) { return o ^ ((o >> 3) & 0x70); }

__device__ __forceinline__ void split_pair(float2 v, uint32_t& h2, uint32_t& l2) {
    asm("cvt.rn.bf16x2.f32 %0, %1, %2;" : "=r"(h2) : "f"(v.y), "f"(v.x));
    float lx = v.x - __uint_as_float(h2 << 16);
    float ly = v.y - __uint_as_float(h2 & 0xffff0000u);
    asm("cvt.rn.bf16x2.f32 %0, %1, %2;" : "=r"(l2) : "f"(ly), "f"(lx));
}

__device__ __forceinline__ void ldsm4(uint32_t* r, uint32_t addr) {
    asm volatile("ldmatrix.sync.aligned.m8n8.x4.shared.b16 {%0,%1,%2,%3}, [%4];"
                 : "=r"(r[0]), "=r"(r[1]), "=r"(r[2]), "=r"(r[3]) : "r"(addr));
}

__device__ __forceinline__ void mma16816(float* c, const uint32_t* a, const uint32_t* b) {
    asm volatile(
        "mma.sync.aligned.m16n8k16.row.col.f32.bf16.bf16.f32 "
        "{%0,%1,%2,%3}, {%4,%5,%6,%7}, {%8,%9}, {%0,%1,%2,%3};"
        : "+f"(c[0]), "+f"(c[1]), "+f"(c[2]), "+f"(c[3])
        : "r"(a[0]), "r"(a[1]), "r"(a[2]), "r"(a[3]), "r"(b[0]), "r"(b[1]));
}

// ---------------- CSR build ----------------
__global__ void zero_cnt_k() {
    int i = blockIdx.x * blockDim.x + threadIdx.x;
    if (i < 2 * NN) g_cnt[i] = 0;
}
// both edge sets in one launch (independent atomics)
__global__ void hist2_k(const int* __restrict__ pdst, const int* __restrict__ ndst) {
    for (int i = blockIdx.x * blockDim.x + threadIdx.x; i < 2 * EE; i += gridDim.x * blockDim.x) {
        if (i < EE) atomicAdd(&g_cnt[pdst[i]], 1);
        else        atomicAdd(&g_cnt[NN + ndst[i - EE]], 1);
    }
}
__global__ void scan1_k(int which) {
    const int* cnt = g_cnt + which * NN;
    int* incl = which ? g_rp_neg : g_rp_pos;
    int* bsum = which ? g_bsum_neg : g_bsum_pos;
    __shared__ int sh[1024];
    int i = blockIdx.x * 1024 + threadIdx.x;
    int v = (i < NN) ? cnt[i] : 0;
    sh[threadIdx.x] = v;
    __syncthreads();
    for (int off = 1; off < 1024; off <<= 1) {
        int t = (threadIdx.x >= off) ? sh[threadIdx.x - off] : 0;
        __syncthreads();
        sh[threadIdx.x] += t;
        __syncthreads();
    }
    if (i < NN) incl[i] = sh[threadIdx.x];
    if (threadIdx.x == 1023) bsum[blockIdx.x] = sh[1023];
}
__global__ void scan2_k(int nb, int which) {
    int* bsum = which ? g_bsum_neg : g_bsum_pos;
    __shared__ int sh[128];
    int v = (threadIdx.x < nb) ? bsum[threadIdx.x] : 0;
    sh[threadIdx.x] = v;
    __syncthreads();
    for (int off = 1; off < 128; off <<= 1) {
        int t = (threadIdx.x >= off) ? sh[threadIdx.x - off] : 0;
        __syncthreads();
        sh[threadIdx.x] += t;
        __syncthreads();
    }
    if (threadIdx.x < nb) bsum[threadIdx.x] = sh[threadIdx.x] - v;
}
__global__ void scan3_k(int which) {
    const int* cnt = g_cnt + which * NN;
    int* rp = which ? g_rp_neg : g_rp_pos;
    int* cur = which ? g_cur_neg : g_cur_pos;
    float* inv = which ? g_inv_neg : g_inv_pos;
    const int* bsum = which ? g_bsum_neg : g_bsum_pos;
    int i = blockIdx.x * blockDim.x + threadIdx.x;
    if (i < NN) {
        int inc = rp[i] + bsum[i >> 10];
        int c = cnt[i];
        int ex = inc - c;
        rp[i] = ex;
        cur[i] = ex;
        inv[i] = 1.0f / (float)(c > 0 ? c : 1);
    }
    if (i == 0) rp[NN] = EE;
}
__global__ void scatter_k(const int* __restrict__ src, const int* __restrict__ dst, int which) {
    int* cur = which ? g_cur_neg : g_cur_pos;
    int* out = which ? g_src_neg : g_src_pos;
    for (int i = blockIdx.x * blockDim.x + threadIdx.x; i < EE; i += gridDim.x * blockDim.x) {
        int d = dst[i];
        int p = atomicAdd(&cur[d], 1);
        out[p] = src[i];
    }
}

// ---------------- weight prep: fp32 -> bf16 hi/lo, [n][k] rows, SW128-swizzled 64-k chunks ----------------
__global__ void prep_w_k(const float* __restrict__ Wl_pos, const float* __restrict__ Wr_pos,
                         const float* __restrict__ Wl_neg, const float* __restrict__ Wr_neg,
                         const float* __restrict__ Wp_l, const float* __restrict__ Wn_l,
                         const float* __restrict__ Wp_r, const float* __restrict__ Wn_r) {
    int idx = blockIdx.x * blockDim.x + threadIdx.x;
    float2 v;
    uint32_t off;
    if (idx < 24576) {
        int stack = idx / 6144, rem = idx % 6144;
        int n = rem / 96, kp = rem % 96, k = kp * 2;
        int l = stack >> 1, h = stack & 1;
        const float* WL = h ? Wl_neg : Wl_pos;  // [2][128][64]
        const float* WR = h ? Wr_neg : Wr_pos;  // [2][64][64]
        if (k < 128) {
            v.x = WL[l * 8192 + k * 64 + n];
            v.y = WL[l * 8192 + (k + 1) * 64 + n];
        } else {
            int kk = k - 128;
            v.x = WR[l * 4096 + kk * 64 + n];
            v.y = WR[l * 4096 + (kk + 1) * 64 + n];
        }
        off = (uint32_t)stack * 24576u + (uint32_t)(k >> 6) * 8192u + swz((uint32_t)n * 128u + (k & 63) * 2u);
    } else if (idx < 24576 + 16384) {
        int j = idx - 24576;
        int colsel = j / 8192, rem = j % 8192;
        int n = rem / 64, kp = rem % 64, k = kp * 2;
        const float* W = (n < 64) ? (colsel ? Wp_r : Wp_l) : (colsel ? Wn_r : Wn_l);
        int nn = n & 63;
        v.x = W[k * 64 + nn];
        v.y = W[(k + 1) * 64 + nn];
        off = 98304u + (uint32_t)colsel * 32768u + (uint32_t)(k >> 6) * 16384u + swz((uint32_t)n * 128u + (k & 63) * 2u);
    } else {
        return;
    }
    uint32_t h2, l2;
    split_pair(v, h2, l2);
    g_WB_h[off >> 2] = h2;
    g_WB_l[off >> 2] = l2;
}

// ---------------- unified HMMA GEMM ----------------
__global__ void __launch_bounds__(256) mma_gemm_k(
    const float* __restrict__ A0, const __half* __restrict__ A1h, int zOff, int nkc,
    int bBase, int bStride,
    float* __restrict__ outF, __half* __restrict__ outH, int outOff,
    const float* __restrict__ bias, int act, int outHalf)
{
    __shared__ uint32_t sAh[4096], sAl[4096];
    __shared__ uint32_t sBh[2048], sBl[2048];
    int tid = threadIdx.x, wid = tid >> 5, lane = tid & 31;
    int v0 = blockIdx.x * 128;

    uint32_t aHb = smem_u32(sAh), aLb = smem_u32(sAl);
    uint32_t bHb = smem_u32(sBh), bLb = smem_u32(sBl);

    int lr = lane & 7, g = lane >> 3;
    int arow = wid * 16 + lr + (g & 1) * 8;
    uint32_t aPreH = aHb + arow * 128, aPreL = aLb + arow * 128;
    uint32_t xmA = (uint32_t)(arow & 7) * 16;
    uint32_t kbA = (uint32_t)(g >> 1) * 16;
    int brow = lr + (g >> 1) * 8;
    uint32_t xmB = (uint32_t)lr * 16;
    uint32_t kbB = (uint32_t)(g & 1) * 16;

    float acc[8][4] = {};

    for (int kc = 0; kc < nkc; kc++) {
        {
            const uint4* bh = (const uint4*)((const char*)g_WB_h + bBase + kc * bStride);
            const uint4* bl = (const uint4*)((const char*)g_WB_l + bBase + kc * bStride);
            for (int i = tid; i < 512; i += 256) {
                ((uint4*)sBh)[i] = bh[i];
                ((uint4*)sBl)[i] = bl[i];
            }
        }
        for (int idx = tid; idx < 4096; idx += 256) {
            int r = idx >> 5, kp = idx & 31;
            float2 v = make_float2(0.f, 0.f);
            if (v0 + r < NN) {
                if (kc == 2)
                    v = __half22float2(*(const __half2*)(A1h + (size_t)(v0 + r) * 128 + zOff + kp * 2));
                else
                    v = *(const float2*)(A0 + (size_t)(v0 + r) * 128 + kc * 64 + kp * 2);
            }
            uint32_t h2, l2;
            split_pair(v, h2, l2);
            uint32_t o = swz((uint32_t)r * 128u + (uint32_t)kp * 4u);
            *(uint32_t*)((char*)sAh + o) = h2;
            *(uint32_t*)((char*)sAl + o) = l2;
        }
        __syncthreads();

#pragma unroll
        for (int ks = 0; ks < 4; ks++) {
            uint32_t kb = ks * 32;
            uint32_t ah[4], al[4];
            ldsm4(ah, aPreH + ((kb + kbA) ^ xmA));
            ldsm4(al, aPreL + ((kb + kbA) ^ xmA));
#pragma unroll
            for (int nt2 = 0; nt2 < 4; nt2++) {
                int n = nt2 * 16 + brow;
                uint32_t bo = (uint32_t)n * 128 + ((kb + kbB) ^ xmB);
                uint32_t bh4[4], bl4[4];
                ldsm4(bh4, bHb + bo);
                ldsm4(bl4, bLb + bo);
                mma16816(acc[nt2 * 2],     ah, bh4);
                mma16816(acc[nt2 * 2 + 1], ah, bh4 + 2);
                mma16816(acc[nt2 * 2],     al, bh4);
                mma16816(acc[nt2 * 2 + 1], al, bh4 + 2);
                mma16816(acc[nt2 * 2],     ah, bl4);
                mma16816(acc[nt2 * 2 + 1], ah, bl4 + 2);
            }
        }
        __syncthreads();
    }

    int r0 = v0 + wid * 16 + (lane >> 2);
    int cb = (lane & 3) * 2;
#pragma unroll
    for (int j = 0; j < 8; j++) {
        int col = j * 8 + cb;
        float bx = 0.f, by = 0.f;
        if (bias) { bx = bias[col]; by = bias[col + 1]; }
        float ox = acc[j][0] + bx, oy = acc[j][1] + by;
        float px = acc[j][2] + bx, py = acc[j][3] + by;
        if (act) { ox = tanhf(ox); oy = tanhf(oy); px = tanhf(px); py = tanhf(py); }
        if (outHalf) {
            if (r0 < NN)     *(__half2*)(outH + (size_t)r0 * 128 + outOff + col)       = __floats2half2_rn(ox, oy);
            if (r0 + 8 < NN) *(__half2*)(outH + (size_t)(r0 + 8) * 128 + outOff + col) = __floats2half2_rn(px, py);
        } else {
            if (r0 < NN)     *(float2*)(outF + (size_t)r0 * 128 + outOff + col)       = make_float2(ox, oy);
            if (r0 + 8 < NN) *(float2*)(outF + (size_t)(r0 + 8) * 128 + outOff + col) = make_float2(px, py);
        }
    }
}

// ---------------- Layer 0: warp-per-node fp16 mean-gather + self + bias + tanh ----------------
__global__ void layer0_k(const float* __restrict__ bp, const float* __restrict__ bn) {
    int v = (blockIdx.x * blockDim.x + threadIdx.x) >> 5;
    int lane = threadIdx.x & 31;
    if (v >= NN) return;
    int c2 = lane * 2;
    float ax = 0.f, ay = 0.f, nx = 0.f, ny = 0.f;
    int b = g_rp_pos[v], e = g_rp_pos[v + 1];
#pragma unroll 4
    for (int i = b; i < e; i++) {
        int s = g_src_pos[i];
        float2 t = __half22float2(*(const __half2*)(g_U0h + (size_t)s * 128 + c2));
        ax += t.x; ay += t.y;
    }
    b = g_rp_neg[v]; e = g_rp_neg[v + 1];
#pragma unroll 4
    for (int i = b; i < e; i++) {
        int s = g_src_neg[i];
        float2 t = __half22float2(*(const __half2*)(g_U0h + (size_t)s * 128 + 64 + c2));
        nx += t.x; ny += t.y;
    }
    float ipv = g_inv_pos[v], inv = g_inv_neg[v];
    float2 sp = *(const float2*)(g_U0s + (size_t)v * 128 + c2);
    float2 sn = *(const float2*)(g_U0s + (size_t)v * 128 + 64 + c2);
    float2 b1 = *(const float2*)(bp + c2);
    float2 b2 = *(const float2*)(bn + c2);
    float zpx = tanhf(ax * ipv + sp.x + b1.x), zpy = tanhf(ay * ipv + sp.y + b1.y);
    float znx = tanhf(nx * inv + sn.x + b2.x), zny = tanhf(ny * inv + sn.y + b2.y);
    *(__half2*)(g_Zh + (size_t)v * 128 + c2) = __floats2half2_rn(zpx, zpy);
    *(__half2*)(g_Zh + (size_t)v * 128 + 64 + c2) = __floats2half2_rn(znx, zny);
}

// ---------------- Layer aggregation: warp-per-node fp16 gather, permuted fp32 output ----------------
__global__ void agg_k(int zsel) {
    const __half* Z = zsel ? g_Z2h : g_Zh;
    int v = (blockIdx.x * blockDim.x + threadIdx.x) >> 5;
    int lane = threadIdx.x & 31;
    if (v >= NN) return;
    int c4 = lane * 4;
    float4 aP = make_float4(0.f, 0.f, 0.f, 0.f);
    float4 aN = make_float4(0.f, 0.f, 0.f, 0.f);
    int b = g_rp_pos[v], e = g_rp_pos[v + 1];
#pragma unroll 4
    for (int i = b; i < e; i++) {
        int s = g_src_pos[i];
        uint2 raw = *(const uint2*)(Z + (size_t)s * 128 + c4);
        float2 f0 = __half22float2(*(const __half2*)&raw.x);
        float2 f1 = __half22float2(*(const __half2*)&raw.y);
        aP.x += f0.x; aP.y += f0.y; aP.z += f1.x; aP.w += f1.y;
    }
    b = g_rp_neg[v]; e = g_rp_neg[v + 1];
#pragma unroll 4
    for (int i = b; i < e; i++) {
        int s = g_src_neg[i];
        uint2 raw = *(const uint2*)(Z + (size_t)s * 128 + c4);
        float2 f0 = __half22float2(*(const __half2*)&raw.x);
        float2 f1 = __half22float2(*(const __half2*)&raw.y);
        aN.x += f0.x; aN.y += f0.y; aN.z += f1.x; aN.w += f1.y;
    }
    float ipv = g_inv_pos[v], inv = g_inv_neg[v];
    aP.x *= ipv; aP.y *= ipv; aP.z *= ipv; aP.w *= ipv;
    aN.x *= inv; aN.y *= inv; aN.z *= inv; aN.w *= inv;
    if (lane < 16) {
        *(float4*)(g_AGGP + (size_t)v * 128 + c4) = aP;
        *(float4*)(g_AGGN + (size_t)v * 128 + 64 + c4) = aN;
    } else {
        *(float4*)(g_AGGP + (size_t)v * 128 + c4) = aN;
        *(float4*)(g_AGGN + (size_t)v * 128 + c4 - 64) = aP;
    }
}

// ---------------- host launcher (single stream, capture-safe) ----------------
extern "C" void kernel_launch(void* const* d_in, const int* in_sizes, int n_in,
                              void* d_out, int out_size) {
    const float* x = (const float*)d_in[0];
    const int* pe = (const int*)d_in[1];   // int32 (JAX x64 disabled)
    const int* ne = (const int*)d_in[2];
    const float* Wp_l = (const float*)d_in[3];
    const float* Wp_r = (const float*)d_in[4];
    const float* bp = (const float*)d_in[5];
    const float* Wn_l = (const float*)d_in[6];
    const float* Wn_r = (const float*)d_in[7];
    const float* bn = (const float*)d_in[8];
    const float* Wl_pos = (const float*)d_in[9];
    const float* Wr_pos = (const float*)d_in[10];
    const float* b_pos = (const float*)d_in[11];
    const float* Wl_neg = (const float*)d_in[12];
    const float* Wr_neg = (const float*)d_in[13];
    const float* b_neg = (const float*)d_in[14];
    float* out = (float*)d_out;

    float *dU0s, *dAGGP, *dAGGN;
    __half *dU0h, *dZh, *dZ2h;
    cudaGetSymbolAddress((void**)&dU0h, g_U0h);
    cudaGetSymbolAddress((void**)&dU0s, g_U0s);
    cudaGetSymbolAddress((void**)&dZh, g_Zh);
    cudaGetSymbolAddress((void**)&dZ2h, g_Z2h);
    cudaGetSymbolAddress((void**)&dAGGP, g_AGGP);
    cudaGetSymbolAddress((void**)&dAGGN, g_AGGN);

    // --- weight prep ---
    prep_w_k<<<160, 256>>>(Wl_pos, Wr_pos, Wl_neg, Wr_neg, Wp_l, Wn_l, Wp_r, Wn_r);

    // --- CSR build (single stream) ---
    zero_cnt_k<<<(2 * NN + 255) / 256, 256>>>();
    hist2_k<<<2048, 256>>>(pe + EE, ne + EE);
    const int NB = (NN + 1023) / 1024;
    scan1_k<<<NB, 1024>>>(0);
    scan2_k<<<1, 128>>>(NB, 0);
    scan3_k<<<(NN + 255) / 256, 256>>>(0);
    scatter_k<<<1024, 256>>>(pe, pe + EE, 0);
    scan1_k<<<NB, 1024>>>(1);
    scan2_k<<<1, 128>>>(NB, 1);
    scan3_k<<<(NN + 255) / 256, 256>>>(1);
    scatter_k<<<1024, 256>>>(ne, ne + EE, 1);

    const int NBT = (NN + 127) / 128;  // 782

    // --- layer 0 pre-GEMMs ---
    for (int h = 0; h < 2; h++) {
        mma_gemm_k<<<NBT, 256>>>(x, nullptr, 0, 2, 98304 + 0 * 32768 + h * 8192, 16384,
                                 nullptr, dU0h, h * 64, nullptr, 0, 1);
        mma_gemm_k<<<NBT, 256>>>(x, nullptr, 0, 2, 98304 + 1 * 32768 + h * 8192, 16384,
                                 dU0s, nullptr, h * 64, nullptr, 0, 0);
    }
    const int NBW = (NN * 32 + 255) / 256;
    layer0_k<<<NBW, 256>>>(bp, bn);

    // --- layer 1 ---
    agg_k<<<NBW, 256>>>(0);
    mma_gemm_k<<<NBT, 256>>>(dAGGP, dZh, 0, 3, 0 * 24576, 8192, nullptr, dZ2h, 0, b_pos, 1, 1);
    mma_gemm_k<<<NBT, 256>>>(dAGGN, dZh, 64, 3, 1 * 24576, 8192, nullptr, dZ2h, 64, b_neg, 1, 1);

    // --- layer 2 ---
    agg_k<<<NBW, 256>>>(1);
    mma_gemm_k<<<NBT, 256>>>(dAGGP, dZ2h, 0, 3, 2 * 24576, 8192, out, nullptr, 0, b_pos + 64, 1, 0);
    mma_gemm_k<<<NBT, 256>>>(dAGGN, dZ2h, 64, 3, 3 * 24576, 8192, out, nullptr, 64, b_neg + 64, 1, 0);
}

// round 11
// speedup vs baseline: 1.5317x; 1.0785x over previous
#include <cuda_runtime.h>
#include <cuda_fp16.h>
#include <cstdint>

#define NN 100000
#define EE 1200000

// ---------------- device scratch (static, allocation-free) ----------------
__device__ int   g_cnt[2 * NN];
__device__ int   g_rp_pos[NN + 1];
__device__ int   g_rp_neg[NN + 1];
__device__ int   g_cur_pos[NN];
__device__ int   g_cur_neg[NN];
__device__ float g_inv_pos[NN];
__device__ float g_inv_neg[NN];
__device__ int   g_src_pos[EE];
__device__ int   g_src_neg[EE];
__device__ int   g_bsum_pos[128];
__device__ int   g_bsum_neg[128];
__device__ __align__(16) __half g_U0h[NN * 128];  // [yp(64) | yn(64)] fp16 (gathered by layer0)
__device__ float g_U0s[NN * 128];                  // [sp(64) | sn(64)] fp32 (self terms)
__device__ __align__(16) __half g_Zh[NN * 128];   // z after layer 0 (fp16)
__device__ __align__(16) __half g_Z2h[NN * 128];  // z after layer 1 (fp16)
__device__ float g_AGGP[NN * 128];  // [Apos[0:64] | Aneg[64:128]]
__device__ float g_AGGN[NN * 128];  // [Apos[64:128] | Aneg[0:64]]

// packed bf16 weights: 4 layer stacks (24576 B each) then gemm0 (2 x 32768 B) = 163840 B
__device__ __align__(16) uint32_t g_WB_h[40960];
__device__ __align__(16) uint32_t g_WB_l[40960];

// ---------------- helpers ----------------
__device__ __forceinline__ uint32_t smem_u32(const void* p) {
    uint32_t a;
    asm("{ .reg .u64 t; cvta.to.shared.u64 t, %1; cvt.u32.u64 %0, t; }" : "=r"(a) : "l"(p));
    return a;
}
__device__ __forceinline__ uint32_t swz(uint32_t o) { return o ^ ((o >> 3) & 0x70); }

__device__ __forceinline__ void split_pair(float2 v, uint32_t& h2, uint32_t& l2) {
    asm("cvt.rn.bf16x2.f32 %0, %1, %2;" : "=r"(h2) : "f"(v.y), "f"(v.x));
    float lx = v.x - __uint_as_float(h2 << 16);
    float ly = v.y - __uint_as_float(h2 & 0xffff0000u);
    asm("cvt.rn.bf16x2.f32 %0, %1, %2;" : "=r"(l2) : "f"(ly), "f"(lx));
}

__device__ __forceinline__ void ldsm4(uint32_t* r, uint32_t addr) {
    asm volatile("ldmatrix.sync.aligned.m8n8.x4.shared.b16 {%0,%1,%2,%3}, [%4];"
                 : "=r"(r[0]), "=r"(r[1]), "=r"(r[2]), "=r"(r[3]) : "r"(addr));
}

__device__ __forceinline__ void mma16816(float* c, const uint32_t* a, const uint32_t* b) {
    asm volatile(
        "mma.sync.aligned.m16n8k16.row.col.f32.bf16.bf16.f32 "
        "{%0,%1,%2,%3}, {%4,%5,%6,%7}, {%8,%9}, {%0,%1,%2,%3};"
        : "+f"(c[0]), "+f"(c[1]), "+f"(c[2]), "+f"(c[3])
        : "r"(a[0]), "r"(a[1]), "r"(a[2]), "r"(a[3]), "r"(b[0]), "r"(b[1]));
}

// ---------------- CSR build ----------------
__global__ void zero_cnt_k() {
    int i = blockIdx.x * blockDim.x + threadIdx.x;
    if (i < 2 * NN) g_cnt[i] = 0;
}
// both edge sets in one launch (independent atomics)
__global__ void hist2_k(const int* __restrict__ pdst, const int* __restrict__ ndst) {
    for (int i = blockIdx.x * blockDim.x + threadIdx.x; i < 2 * EE; i += gridDim.x * blockDim.x) {
        if (i < EE) atomicAdd(&g_cnt[pdst[i]], 1);
        else        atomicAdd(&g_cnt[NN + ndst[i - EE]], 1);
    }
}
// merged scans: both edge sets per launch
__global__ void scan1m_k() {
    int which = blockIdx.y;
    const int* cnt = g_cnt + which * NN;
    int* incl = which ? g_rp_neg : g_rp_pos;
    int* bsum = which ? g_bsum_neg : g_bsum_pos;
    __shared__ int sh[1024];
    int i = blockIdx.x * 1024 + threadIdx.x;
    int v = (i < NN) ? cnt[i] : 0;
    sh[threadIdx.x] = v;
    __syncthreads();
    for (int off = 1; off < 1024; off <<= 1) {
        int t = (threadIdx.x >= off) ? sh[threadIdx.x - off] : 0;
        __syncthreads();
        sh[threadIdx.x] += t;
        __syncthreads();
    }
    if (i < NN) incl[i] = sh[threadIdx.x];
    if (threadIdx.x == 1023) bsum[blockIdx.x] = sh[1023];
}
__global__ void scan2m_k(int nb) {
    int which = blockIdx.x;
    int* bsum = which ? g_bsum_neg : g_bsum_pos;
    __shared__ int sh[128];
    int v = (threadIdx.x < nb) ? bsum[threadIdx.x] : 0;
    sh[threadIdx.x] = v;
    __syncthreads();
    for (int off = 1; off < 128; off <<= 1) {
        int t = (threadIdx.x >= off) ? sh[threadIdx.x - off] : 0;
        __syncthreads();
        sh[threadIdx.x] += t;
        __syncthreads();
    }
    if (threadIdx.x < nb) bsum[threadIdx.x] = sh[threadIdx.x] - v;
}
__global__ void scan3m_k() {
    int which = blockIdx.y;
    const int* cnt = g_cnt + which * NN;
    int* rp = which ? g_rp_neg : g_rp_pos;
    int* cur = which ? g_cur_neg : g_cur_pos;
    float* inv = which ? g_inv_neg : g_inv_pos;
    const int* bsum = which ? g_bsum_neg : g_bsum_pos;
    int i = blockIdx.x * blockDim.x + threadIdx.x;
    if (i < NN) {
        int inc = rp[i] + bsum[i >> 10];
        int c = cnt[i];
        int ex = inc - c;
        rp[i] = ex;
        cur[i] = ex;
        inv[i] = 1.0f / (float)(c > 0 ? c : 1);
    }
    if (i == 0) rp[NN] = EE;
}
// both edge sets in one launch
__global__ void scatter2_k(const int* __restrict__ ps, const int* __restrict__ pd,
                           const int* __restrict__ ns, const int* __restrict__ nd) {
    for (int i = blockIdx.x * blockDim.x + threadIdx.x; i < 2 * EE; i += gridDim.x * blockDim.x) {
        if (i < EE) {
            int d = pd[i];
            int p = atomicAdd(&g_cur_pos[d], 1);
            g_src_pos[p] = ps[i];
        } else {
            int d = nd[i - EE];
            int p = atomicAdd(&g_cur_neg[d], 1);
            g_src_neg[p] = ns[i - EE];
        }
    }
}

// ---------------- weight prep: fp32 -> bf16 hi/lo, [n][k] rows, SW128-swizzled 64-k chunks ----------------
__global__ void prep_w_k(const float* __restrict__ Wl_pos, const float* __restrict__ Wr_pos,
                         const float* __restrict__ Wl_neg, const float* __restrict__ Wr_neg,
                         const float* __restrict__ Wp_l, const float* __restrict__ Wn_l,
                         const float* __restrict__ Wp_r, const float* __restrict__ Wn_r) {
    int idx = blockIdx.x * blockDim.x + threadIdx.x;
    float2 v;
    uint32_t off;
    if (idx < 24576) {
        int stack = idx / 6144, rem = idx % 6144;
        int n = rem / 96, kp = rem % 96, k = kp * 2;
        int l = stack >> 1, h = stack & 1;
        const float* WL = h ? Wl_neg : Wl_pos;  // [2][128][64]
        const float* WR = h ? Wr_neg : Wr_pos;  // [2][64][64]
        if (k < 128) {
            v.x = WL[l * 8192 + k * 64 + n];
            v.y = WL[l * 8192 + (k + 1) * 64 + n];
        } else {
            int kk = k - 128;
            v.x = WR[l * 4096 + kk * 64 + n];
            v.y = WR[l * 4096 + (kk + 1) * 64 + n];
        }
        off = (uint32_t)stack * 24576u + (uint32_t)(k >> 6) * 8192u + swz((uint32_t)n * 128u + (k & 63) * 2u);
    } else if (idx < 24576 + 16384) {
        int j = idx - 24576;
        int colsel = j / 8192, rem = j % 8192;
        int n = rem / 64, kp = rem % 64, k = kp * 2;
        const float* W = (n < 64) ? (colsel ? Wp_r : Wp_l) : (colsel ? Wn_r : Wn_l);
        int nn = n & 63;
        v.x = W[k * 64 + nn];
        v.y = W[(k + 1) * 64 + nn];
        off = 98304u + (uint32_t)colsel * 32768u + (uint32_t)(k >> 6) * 16384u + swz((uint32_t)n * 128u + (k & 63) * 2u);
    } else {
        return;
    }
    uint32_t h2, l2;
    split_pair(v, h2, l2);
    g_WB_h[off >> 2] = h2;
    g_WB_l[off >> 2] = l2;
}

// ---------------- unified HMMA GEMM (layer GEMMs, N=64) ----------------
__global__ void __launch_bounds__(256) mma_gemm_k(
    const float* __restrict__ A0, const __half* __restrict__ A1h, int zOff, int nkc,
    int bBase, int bStride,
    float* __restrict__ outF, __half* __restrict__ outH, int outOff,
    const float* __restrict__ bias, int act, int outHalf)
{
    __shared__ uint32_t sAh[4096], sAl[4096];
    __shared__ uint32_t sBh[2048], sBl[2048];
    int tid = threadIdx.x, wid = tid >> 5, lane = tid & 31;
    int v0 = blockIdx.x * 128;

    uint32_t aHb = smem_u32(sAh), aLb = smem_u32(sAl);
    uint32_t bHb = smem_u32(sBh), bLb = smem_u32(sBl);

    int lr = lane & 7, g = lane >> 3;
    int arow = wid * 16 + lr + (g & 1) * 8;
    uint32_t aPreH = aHb + arow * 128, aPreL = aLb + arow * 128;
    uint32_t xmA = (uint32_t)(arow & 7) * 16;
    uint32_t kbA = (uint32_t)(g >> 1) * 16;
    int brow = lr + (g >> 1) * 8;
    uint32_t xmB = (uint32_t)lr * 16;
    uint32_t kbB = (uint32_t)(g & 1) * 16;

    float acc[8][4] = {};

    for (int kc = 0; kc < nkc; kc++) {
        {
            const uint4* bh = (const uint4*)((const char*)g_WB_h + bBase + kc * bStride);
            const uint4* bl = (const uint4*)((const char*)g_WB_l + bBase + kc * bStride);
            for (int i = tid; i < 512; i += 256) {
                ((uint4*)sBh)[i] = bh[i];
                ((uint4*)sBl)[i] = bl[i];
            }
        }
        for (int idx = tid; idx < 4096; idx += 256) {
            int r = idx >> 5, kp = idx & 31;
            float2 v = make_float2(0.f, 0.f);
            if (v0 + r < NN) {
                if (kc == 2)
                    v = __half22float2(*(const __half2*)(A1h + (size_t)(v0 + r) * 128 + zOff + kp * 2));
                else
                    v = *(const float2*)(A0 + (size_t)(v0 + r) * 128 + kc * 64 + kp * 2);
            }
            uint32_t h2, l2;
            split_pair(v, h2, l2);
            uint32_t o = swz((uint32_t)r * 128u + (uint32_t)kp * 4u);
            *(uint32_t*)((char*)sAh + o) = h2;
            *(uint32_t*)((char*)sAl + o) = l2;
        }
        __syncthreads();

#pragma unroll
        for (int ks = 0; ks < 4; ks++) {
            uint32_t kb = ks * 32;
            uint32_t ah[4], al[4];
            ldsm4(ah, aPreH + ((kb + kbA) ^ xmA));
            ldsm4(al, aPreL + ((kb + kbA) ^ xmA));
#pragma unroll
            for (int nt2 = 0; nt2 < 4; nt2++) {
                int n = nt2 * 16 + brow;
                uint32_t bo = (uint32_t)n * 128 + ((kb + kbB) ^ xmB);
                uint32_t bh4[4], bl4[4];
                ldsm4(bh4, bHb + bo);
                ldsm4(bl4, bLb + bo);
                mma16816(acc[nt2 * 2],     ah, bh4);
                mma16816(acc[nt2 * 2 + 1], ah, bh4 + 2);
                mma16816(acc[nt2 * 2],     al, bh4);
                mma16816(acc[nt2 * 2 + 1], al, bh4 + 2);
                mma16816(acc[nt2 * 2],     ah, bl4);
                mma16816(acc[nt2 * 2 + 1], ah, bl4 + 2);
            }
        }
        __syncthreads();
    }

    int r0 = v0 + wid * 16 + (lane >> 2);
    int cb = (lane & 3) * 2;
#pragma unroll
    for (int j = 0; j < 8; j++) {
        int col = j * 8 + cb;
        float bx = 0.f, by = 0.f;
        if (bias) { bx = bias[col]; by = bias[col + 1]; }
        float ox = acc[j][0] + bx, oy = acc[j][1] + by;
        float px = acc[j][2] + bx, py = acc[j][3] + by;
        if (act) { ox = tanhf(ox); oy = tanhf(oy); px = tanhf(px); py = tanhf(py); }
        if (outHalf) {
            if (r0 < NN)     *(__half2*)(outH + (size_t)r0 * 128 + outOff + col)       = __floats2half2_rn(ox, oy);
            if (r0 + 8 < NN) *(__half2*)(outH + (size_t)(r0 + 8) * 128 + outOff + col) = __floats2half2_rn(px, py);
        } else {
            if (r0 < NN)     *(float2*)(outF + (size_t)r0 * 128 + outOff + col)       = make_float2(ox, oy);
            if (r0 + 8 < NN) *(float2*)(outF + (size_t)(r0 + 8) * 128 + outOff + col) = make_float2(px, py);
        }
    }
}

// ---------------- fused layer-0 GEMM: stage X once, both 64-col halves (K=128) ----------------
__global__ void __launch_bounds__(256) mma_gemm0_dual_k(
    const float* __restrict__ X, int bBase0,
    float* __restrict__ outF, __half* __restrict__ outH, int outHalf)
{
    __shared__ uint32_t sAh[4096], sAl[4096];
    __shared__ uint32_t sBh[2048], sBl[2048];
    int tid = threadIdx.x, wid = tid >> 5, lane = tid & 31;
    int v0 = blockIdx.x * 128;

    uint32_t aHb = smem_u32(sAh), aLb = smem_u32(sAl);
    uint32_t bHb = smem_u32(sBh), bLb = smem_u32(sBl);

    int lr = lane & 7, g = lane >> 3;
    int arow = wid * 16 + lr + (g & 1) * 8;
    uint32_t aPreH = aHb + arow * 128, aPreL = aLb + arow * 128;
    uint32_t xmA = (uint32_t)(arow & 7) * 16;
    uint32_t kbA = (uint32_t)(g >> 1) * 16;
    int brow = lr + (g >> 1) * 8;
    uint32_t xmB = (uint32_t)lr * 16;
    uint32_t kbB = (uint32_t)(g & 1) * 16;

    float acc[2][8][4] = {};

    for (int kc = 0; kc < 2; kc++) {
        // stage A = X chunk, once per kc
        for (int idx = tid; idx < 4096; idx += 256) {
            int r = idx >> 5, kp = idx & 31;
            float2 v = make_float2(0.f, 0.f);
            if (v0 + r < NN) v = *(const float2*)(X + (size_t)(v0 + r) * 128 + kc * 64 + kp * 2);
            uint32_t h2, l2;
            split_pair(v, h2, l2);
            uint32_t o = swz((uint32_t)r * 128u + (uint32_t)kp * 4u);
            *(uint32_t*)((char*)sAh + o) = h2;
            *(uint32_t*)((char*)sAl + o) = l2;
        }
        __syncthreads();

        for (int h = 0; h < 2; h++) {
            // stage B set h, chunk kc
            {
                const uint4* bh = (const uint4*)((const char*)g_WB_h + bBase0 + h * 8192 + kc * 16384);
                const uint4* bl = (const uint4*)((const char*)g_WB_l + bBase0 + h * 8192 + kc * 16384);
                for (int i = tid; i < 512; i += 256) {
                    ((uint4*)sBh)[i] = bh[i];
                    ((uint4*)sBl)[i] = bl[i];
                }
            }
            __syncthreads();
#pragma unroll
            for (int ks = 0; ks < 4; ks++) {
                uint32_t kb = ks * 32;
                uint32_t ah[4], al[4];
                ldsm4(ah, aPreH + ((kb + kbA) ^ xmA));
                ldsm4(al, aPreL + ((kb + kbA) ^ xmA));
#pragma unroll
                for (int nt2 = 0; nt2 < 4; nt2++) {
                    int n = nt2 * 16 + brow;
                    uint32_t bo = (uint32_t)n * 128 + ((kb + kbB) ^ xmB);
                    uint32_t bh4[4], bl4[4];
                    ldsm4(bh4, bHb + bo);
                    ldsm4(bl4, bLb + bo);
                    mma16816(acc[h][nt2 * 2],     ah, bh4);
                    mma16816(acc[h][nt2 * 2 + 1], ah, bh4 + 2);
                    mma16816(acc[h][nt2 * 2],     al, bh4);
                    mma16816(acc[h][nt2 * 2 + 1], al, bh4 + 2);
                    mma16816(acc[h][nt2 * 2],     ah, bl4);
                    mma16816(acc[h][nt2 * 2 + 1], ah, bl4 + 2);
                }
            }
            __syncthreads();
        }
    }

    int r0 = v0 + wid * 16 + (lane >> 2);
    int cb = (lane & 3) * 2;
#pragma unroll
    for (int h = 0; h < 2; h++) {
        int outOff = h * 64;
#pragma unroll
        for (int j = 0; j < 8; j++) {
            int col = j * 8 + cb;
            float ox = acc[h][j][0], oy = acc[h][j][1];
            float px = acc[h][j][2], py = acc[h][j][3];
            if (outHalf) {
                if (r0 < NN)     *(__half2*)(outH + (size_t)r0 * 128 + outOff + col)       = __floats2half2_rn(ox, oy);
                if (r0 + 8 < NN) *(__half2*)(outH + (size_t)(r0 + 8) * 128 + outOff + col) = __floats2half2_rn(px, py);
            } else {
                if (r0 < NN)     *(float2*)(outF + (size_t)r0 * 128 + outOff + col)       = make_float2(ox, oy);
                if (r0 + 8 < NN) *(float2*)(outF + (size_t)(r0 + 8) * 128 + outOff + col) = make_float2(px, py);
            }
        }
    }
}

// ---------------- Layer 0: warp-per-node fp16 mean-gather + self + bias + tanh ----------------
__global__ void layer0_k(const float* __restrict__ bp, const float* __restrict__ bn) {
    int v = (blockIdx.x * blockDim.x + threadIdx.x) >> 5;
    int lane = threadIdx.x & 31;
    if (v >= NN) return;
    int c2 = lane * 2;
    float ax = 0.f, ay = 0.f, nx = 0.f, ny = 0.f;
    int b = g_rp_pos[v], e = g_rp_pos[v + 1];
#pragma unroll 4
    for (int i = b; i < e; i++) {
        int s = g_src_pos[i];
        float2 t = __half22float2(*(const __half2*)(g_U0h + (size_t)s * 128 + c2));
        ax += t.x; ay += t.y;
    }
    b = g_rp_neg[v]; e = g_rp_neg[v + 1];
#pragma unroll 4
    for (int i = b; i < e; i++) {
        int s = g_src_neg[i];
        float2 t = __half22float2(*(const __half2*)(g_U0h + (size_t)s * 128 + 64 + c2));
        nx += t.x; ny += t.y;
    }
    float ipv = g_inv_pos[v], inv = g_inv_neg[v];
    float2 sp = *(const float2*)(g_U0s + (size_t)v * 128 + c2);
    float2 sn = *(const float2*)(g_U0s + (size_t)v * 128 + 64 + c2);
    float2 b1 = *(const float2*)(bp + c2);
    float2 b2 = *(const float2*)(bn + c2);
    float zpx = tanhf(ax * ipv + sp.x + b1.x), zpy = tanhf(ay * ipv + sp.y + b1.y);
    float znx = tanhf(nx * inv + sn.x + b2.x), zny = tanhf(ny * inv + sn.y + b2.y);
    *(__half2*)(g_Zh + (size_t)v * 128 + c2) = __floats2half2_rn(zpx, zpy);
    *(__half2*)(g_Zh + (size_t)v * 128 + 64 + c2) = __floats2half2_rn(znx, zny);
}

// ---------------- Layer aggregation: warp-per-node fp16 gather, permuted fp32 output ----------------
__global__ void agg_k(int zsel) {
    const __half* Z = zsel ? g_Z2h : g_Zh;
    int v = (blockIdx.x * blockDim.x + threadIdx.x) >> 5;
    int lane = threadIdx.x & 31;
    if (v >= NN) return;
    int c4 = lane * 4;
    float4 aP = make_float4(0.f, 0.f, 0.f, 0.f);
    float4 aN = make_float4(0.f, 0.f, 0.f, 0.f);
    int b = g_rp_pos[v], e = g_rp_pos[v + 1];
#pragma unroll 4
    for (int i = b; i < e; i++) {
        int s = g_src_pos[i];
        uint2 raw = *(const uint2*)(Z + (size_t)s * 128 + c4);
        float2 f0 = __half22float2(*(const __half2*)&raw.x);
        float2 f1 = __half22float2(*(const __half2*)&raw.y);
        aP.x += f0.x; aP.y += f0.y; aP.z += f1.x; aP.w += f1.y;
    }
    b = g_rp_neg[v]; e = g_rp_neg[v + 1];
#pragma unroll 4
    for (int i = b; i < e; i++) {
        int s = g_src_neg[i];
        uint2 raw = *(const uint2*)(Z + (size_t)s * 128 + c4);
        float2 f0 = __half22float2(*(const __half2*)&raw.x);
        float2 f1 = __half22float2(*(const __half2*)&raw.y);
        aN.x += f0.x; aN.y += f0.y; aN.z += f1.x; aN.w += f1.y;
    }
    float ipv = g_inv_pos[v], inv = g_inv_neg[v];
    aP.x *= ipv; aP.y *= ipv; aP.z *= ipv; aP.w *= ipv;
    aN.x *= inv; aN.y *= inv; aN.z *= inv; aN.w *= inv;
    if (lane < 16) {
        *(float4*)(g_AGGP + (size_t)v * 128 + c4) = aP;
        *(float4*)(g_AGGN + (size_t)v * 128 + 64 + c4) = aN;
    } else {
        *(float4*)(g_AGGP + (size_t)v * 128 + c4) = aN;
        *(float4*)(g_AGGN + (size_t)v * 128 + c4 - 64) = aP;
    }
}

// ---------------- host launcher (single stream, capture-safe) ----------------
extern "C" void kernel_launch(void* const* d_in, const int* in_sizes, int n_in,
                              void* d_out, int out_size) {
    const float* x = (const float*)d_in[0];
    const int* pe = (const int*)d_in[1];   // int32 (JAX x64 disabled)
    const int* ne = (const int*)d_in[2];
    const float* Wp_l = (const float*)d_in[3];
    const float* Wp_r = (const float*)d_in[4];
    const float* bp = (const float*)d_in[5];
    const float* Wn_l = (const float*)d_in[6];
    const float* Wn_r = (const float*)d_in[7];
    const float* bn = (const float*)d_in[8];
    const float* Wl_pos = (const float*)d_in[9];
    const float* Wr_pos = (const float*)d_in[10];
    const float* b_pos = (const float*)d_in[11];
    const float* Wl_neg = (const float*)d_in[12];
    const float* Wr_neg = (const float*)d_in[13];
    const float* b_neg = (const float*)d_in[14];
    float* out = (float*)d_out;

    float *dU0s, *dAGGP, *dAGGN;
    __half *dU0h, *dZh, *dZ2h;
    cudaGetSymbolAddress((void**)&dU0h, g_U0h);
    cudaGetSymbolAddress((void**)&dU0s, g_U0s);
    cudaGetSymbolAddress((void**)&dZh, g_Zh);
    cudaGetSymbolAddress((void**)&dZ2h, g_Z2h);
    cudaGetSymbolAddress((void**)&dAGGP, g_AGGP);
    cudaGetSymbolAddress((void**)&dAGGN, g_AGGN);

    // --- weight prep ---
    prep_w_k<<<160, 256>>>(Wl_pos, Wr_pos, Wl_neg, Wr_neg, Wp_l, Wn_l, Wp_r, Wn_r);

    // --- CSR build (single stream, merged launches) ---
    zero_cnt_k<<<(2 * NN + 255) / 256, 256>>>();
    hist2_k<<<2048, 256>>>(pe + EE, ne + EE);
    const int NB = (NN + 1023) / 1024;
    { dim3 grd(NB, 2); scan1m_k<<<grd, 1024>>>(); }
    scan2m_k<<<2, 128>>>(NB);
    { dim3 grd((NN + 255) / 256, 2); scan3m_k<<<grd, 256>>>(); }
    scatter2_k<<<2048, 256>>>(pe, pe + EE, ne, ne + EE);

    const int NBT = (NN + 127) / 128;  // 782

    // --- layer 0 pre-GEMMs (fused halves: 2 launches, X read once each) ---
    mma_gemm0_dual_k<<<NBT, 256>>>(x, 98304,         nullptr, dU0h, 1);  // left weights -> gathered (fp16)
    mma_gemm0_dual_k<<<NBT, 256>>>(x, 98304 + 32768, dU0s,  nullptr, 0); // right weights -> self (fp32)
    const int NBW = (NN * 32 + 255) / 256;
    layer0_k<<<NBW, 256>>>(bp, bn);

    // --- layer 1 ---
    agg_k<<<NBW, 256>>>(0);
    mma_gemm_k<<<NBT, 256>>>(dAGGP, dZh, 0, 3, 0 * 24576, 8192, nullptr, dZ2h, 0, b_pos, 1, 1);
    mma_gemm_k<<<NBT, 256>>>(dAGGN, dZh, 64, 3, 1 * 24576, 8192, nullptr, dZ2h, 64, b_neg, 1, 1);

    // --- layer 2 ---
    agg_k<<<NBW, 256>>>(1);
    mma_gemm_k<<<NBT, 256>>>(dAGGP, dZ2h, 0, 3, 2 * 24576, 8192, out, nullptr, 0, b_pos + 64, 1, 0);
    mma_gemm_k<<<NBT, 256>>>(dAGGN, dZ2h, 64, 3, 3 * 24576, 8192, out, nullptr, 64, b_neg + 64, 1, 0);
}

// round 12
// speedup vs baseline: 1.6168x; 1.0555x over previous
#include <cuda_runtime.h>
#include <cuda_fp16.h>
#include <cstdint>

#define NN 100000
#define EE 1200000

// ---------------- device scratch (static, allocation-free) ----------------
__device__ int   g_cnt[2 * NN];
__device__ int   g_rp_pos[NN + 1];
__device__ int   g_rp_neg[NN + 1];
__device__ int   g_cur_pos[NN];
__device__ int   g_cur_neg[NN];
__device__ float g_inv_pos[NN];
__device__ float g_inv_neg[NN];
__device__ int   g_src_pos[EE];
__device__ int   g_src_neg[EE];
__device__ int   g_bsum_pos[128];
__device__ int   g_bsum_neg[128];
__device__ __align__(16) __half g_U0h[NN * 128];  // [yp(64) | yn(64)] fp16 (gathered by layer0)
__device__ float g_U0s[NN * 128];                  // [sp(64) | sn(64)] fp32 (self terms)
__device__ __align__(16) __half g_Zh[NN * 128];   // z after layer 0 (fp16)
__device__ __align__(16) __half g_Z2h[NN * 128];  // z after layer 1 (fp16)
__device__ float g_AGGP[NN * 128];  // [Apos[0:64] | Aneg[64:128]]
__device__ float g_AGGN[NN * 128];  // [Apos[64:128] | Aneg[0:64]]

// packed bf16 weights: 4 layer stacks (24576 B each) then gemm0 (2 x 32768 B) = 163840 B
__device__ __align__(16) uint32_t g_WB_h[40960];
__device__ __align__(16) uint32_t g_WB_l[40960];

// ---------------- helpers ----------------
__device__ __forceinline__ uint32_t smem_u32(const void* p) {
    uint32_t a;
    asm("{ .reg .u64 t; cvta.to.shared.u64 t, %1; cvt.u32.u64 %0, t; }" : "=r"(a) : "l"(p));
    return a;
}
__device__ __forceinline__ uint32_t swz(uint32_t o) { return o ^ ((o >> 3) & 0x70); }

__device__ __forceinline__ void split_pair(float2 v, uint32_t& h2, uint32_t& l2) {
    asm("cvt.rn.bf16x2.f32 %0, %1, %2;" : "=r"(h2) : "f"(v.y), "f"(v.x));
    float lx = v.x - __uint_as_float(h2 << 16);
    float ly = v.y - __uint_as_float(h2 & 0xffff0000u);
    asm("cvt.rn.bf16x2.f32 %0, %1, %2;" : "=r"(l2) : "f"(ly), "f"(lx));
}

__device__ __forceinline__ void ldsm4(uint32_t* r, uint32_t addr) {
    asm volatile("ldmatrix.sync.aligned.m8n8.x4.shared.b16 {%0,%1,%2,%3}, [%4];"
                 : "=r"(r[0]), "=r"(r[1]), "=r"(r[2]), "=r"(r[3]) : "r"(addr));
}

__device__ __forceinline__ void mma16816(float* c, const uint32_t* a, const uint32_t* b) {
    asm volatile(
        "mma.sync.aligned.m16n8k16.row.col.f32.bf16.bf16.f32 "
        "{%0,%1,%2,%3}, {%4,%5,%6,%7}, {%8,%9}, {%0,%1,%2,%3};"
        : "+f"(c[0]), "+f"(c[1]), "+f"(c[2]), "+f"(c[3])
        : "r"(a[0]), "r"(a[1]), "r"(a[2]), "r"(a[3]), "r"(b[0]), "r"(b[1]));
}

__device__ __forceinline__ void acc_h8(float4& a0, float4& a1, uint4 raw) {
    float2 f0 = __half22float2(*(const __half2*)&raw.x);
    float2 f1 = __half22float2(*(const __half2*)&raw.y);
    float2 f2 = __half22float2(*(const __half2*)&raw.z);
    float2 f3 = __half22float2(*(const __half2*)&raw.w);
    a0.x += f0.x; a0.y += f0.y; a0.z += f1.x; a0.w += f1.y;
    a1.x += f2.x; a1.y += f2.y; a1.z += f3.x; a1.w += f3.y;
}

// ---------------- CSR build ----------------
__global__ void zero_cnt_k() {
    int i = blockIdx.x * blockDim.x + threadIdx.x;
    if (i < 2 * NN) g_cnt[i] = 0;
}
__global__ void hist2_k(const int* __restrict__ pdst, const int* __restrict__ ndst) {
    for (int i = blockIdx.x * blockDim.x + threadIdx.x; i < 2 * EE; i += gridDim.x * blockDim.x) {
        if (i < EE) atomicAdd(&g_cnt[pdst[i]], 1);
        else        atomicAdd(&g_cnt[NN + ndst[i - EE]], 1);
    }
}
__global__ void scan1m_k() {
    int which = blockIdx.y;
    const int* cnt = g_cnt + which * NN;
    int* incl = which ? g_rp_neg : g_rp_pos;
    int* bsum = which ? g_bsum_neg : g_bsum_pos;
    __shared__ int sh[1024];
    int i = blockIdx.x * 1024 + threadIdx.x;
    int v = (i < NN) ? cnt[i] : 0;
    sh[threadIdx.x] = v;
    __syncthreads();
    for (int off = 1; off < 1024; off <<= 1) {
        int t = (threadIdx.x >= off) ? sh[threadIdx.x - off] : 0;
        __syncthreads();
        sh[threadIdx.x] += t;
        __syncthreads();
    }
    if (i < NN) incl[i] = sh[threadIdx.x];
    if (threadIdx.x == 1023) bsum[blockIdx.x] = sh[1023];
}
__global__ void scan2m_k(int nb) {
    int which = blockIdx.x;
    int* bsum = which ? g_bsum_neg : g_bsum_pos;
    __shared__ int sh[128];
    int v = (threadIdx.x < nb) ? bsum[threadIdx.x] : 0;
    sh[threadIdx.x] = v;
    __syncthreads();
    for (int off = 1; off < 128; off <<= 1) {
        int t = (threadIdx.x >= off) ? sh[threadIdx.x - off] : 0;
        __syncthreads();
        sh[threadIdx.x] += t;
        __syncthreads();
    }
    if (threadIdx.x < nb) bsum[threadIdx.x] = sh[threadIdx.x] - v;
}
__global__ void scan3m_k() {
    int which = blockIdx.y;
    const int* cnt = g_cnt + which * NN;
    int* rp = which ? g_rp_neg : g_rp_pos;
    int* cur = which ? g_cur_neg : g_cur_pos;
    float* inv = which ? g_inv_neg : g_inv_pos;
    const int* bsum = which ? g_bsum_neg : g_bsum_pos;
    int i = blockIdx.x * blockDim.x + threadIdx.x;
    if (i < NN) {
        int inc = rp[i] + bsum[i >> 10];
        int c = cnt[i];
        int ex = inc - c;
        rp[i] = ex;
        cur[i] = ex;
        inv[i] = 1.0f / (float)(c > 0 ? c : 1);
    }
    if (i == 0) rp[NN] = EE;
}
__global__ void scatter2_k(const int* __restrict__ ps, const int* __restrict__ pd,
                           const int* __restrict__ ns, const int* __restrict__ nd) {
    for (int i = blockIdx.x * blockDim.x + threadIdx.x; i < 2 * EE; i += gridDim.x * blockDim.x) {
        if (i < EE) {
            int d = pd[i];
            int p = atomicAdd(&g_cur_pos[d], 1);
            g_src_pos[p] = ps[i];
        } else {
            int d = nd[i - EE];
            int p = atomicAdd(&g_cur_neg[d], 1);
            g_src_neg[p] = ns[i - EE];
        }
    }
}

// ---------------- weight prep: fp32 -> bf16 hi/lo, [n][k] rows, SW128-swizzled 64-k chunks ----------------
__global__ void prep_w_k(const float* __restrict__ Wl_pos, const float* __restrict__ Wr_pos,
                         const float* __restrict__ Wl_neg, const float* __restrict__ Wr_neg,
                         const float* __restrict__ Wp_l, const float* __restrict__ Wn_l,
                         const float* __restrict__ Wp_r, const float* __restrict__ Wn_r) {
    int idx = blockIdx.x * blockDim.x + threadIdx.x;
    float2 v;
    uint32_t off;
    if (idx < 24576) {
        int stack = idx / 6144, rem = idx % 6144;
        int n = rem / 96, kp = rem % 96, k = kp * 2;
        int l = stack >> 1, h = stack & 1;
        const float* WL = h ? Wl_neg : Wl_pos;  // [2][128][64]
        const float* WR = h ? Wr_neg : Wr_pos;  // [2][64][64]
        if (k < 128) {
            v.x = WL[l * 8192 + k * 64 + n];
            v.y = WL[l * 8192 + (k + 1) * 64 + n];
        } else {
            int kk = k - 128;
            v.x = WR[l * 4096 + kk * 64 + n];
            v.y = WR[l * 4096 + (kk + 1) * 64 + n];
        }
        off = (uint32_t)stack * 24576u + (uint32_t)(k >> 6) * 8192u + swz((uint32_t)n * 128u + (k & 63) * 2u);
    } else if (idx < 24576 + 16384) {
        int j = idx - 24576;
        int colsel = j / 8192, rem = j % 8192;
        int n = rem / 64, kp = rem % 64, k = kp * 2;
        const float* W = (n < 64) ? (colsel ? Wp_r : Wp_l) : (colsel ? Wn_r : Wn_l);
        int nn = n & 63;
        v.x = W[k * 64 + nn];
        v.y = W[(k + 1) * 64 + nn];
        off = 98304u + (uint32_t)colsel * 32768u + (uint32_t)(k >> 6) * 16384u + swz((uint32_t)n * 128u + (k & 63) * 2u);
    } else {
        return;
    }
    uint32_t h2, l2;
    split_pair(v, h2, l2);
    g_WB_h[off >> 2] = h2;
    g_WB_l[off >> 2] = l2;
}

// ---------------- layer GEMM, both halves in one launch (blockIdx.y = half) ----------------
// out_half = act([AGGh | z_half] @ [Wl;Wr] + b); A chunks 0,1 fp32 from A0, chunk 2 fp16 from A1h.
__global__ void __launch_bounds__(256) mma_layer_dual_k(
    const float* __restrict__ A0a, const float* __restrict__ A0b,
    const __half* __restrict__ A1h, int bBaseA,
    const float* __restrict__ biasA, const float* __restrict__ biasB,
    float* __restrict__ outF, __half* __restrict__ outH, int outHalf)
{
    __shared__ uint32_t sAh[4096], sAl[4096];
    __shared__ uint32_t sBh[2048], sBl[2048];
    int tid = threadIdx.x, wid = tid >> 5, lane = tid & 31;
    int v0 = blockIdx.x * 128;
    int h = blockIdx.y;
    const float* A0 = h ? A0b : A0a;
    const float* bias = h ? biasB : biasA;
    int bBase = bBaseA + h * 24576;
    int zOff = h * 64, outOff = h * 64;

    uint32_t aHb = smem_u32(sAh), aLb = smem_u32(sAl);
    uint32_t bHb = smem_u32(sBh), bLb = smem_u32(sBl);

    int lr = lane & 7, g = lane >> 3;
    int arow = wid * 16 + lr + (g & 1) * 8;
    uint32_t aPreH = aHb + arow * 128, aPreL = aLb + arow * 128;
    uint32_t xmA = (uint32_t)(arow & 7) * 16;
    uint32_t kbA = (uint32_t)(g >> 1) * 16;
    int brow = lr + (g >> 1) * 8;
    uint32_t xmB = (uint32_t)lr * 16;
    uint32_t kbB = (uint32_t)(g & 1) * 16;

    float acc[8][4] = {};

    for (int kc = 0; kc < 3; kc++) {
        {
            const uint4* bh = (const uint4*)((const char*)g_WB_h + bBase + kc * 8192);
            const uint4* bl = (const uint4*)((const char*)g_WB_l + bBase + kc * 8192);
            for (int i = tid; i < 512; i += 256) {
                ((uint4*)sBh)[i] = bh[i];
                ((uint4*)sBl)[i] = bl[i];
            }
        }
        for (int idx = tid; idx < 4096; idx += 256) {
            int r = idx >> 5, kp = idx & 31;
            float2 v = make_float2(0.f, 0.f);
            if (v0 + r < NN) {
                if (kc == 2)
                    v = __half22float2(*(const __half2*)(A1h + (size_t)(v0 + r) * 128 + zOff + kp * 2));
                else
                    v = *(const float2*)(A0 + (size_t)(v0 + r) * 128 + kc * 64 + kp * 2);
            }
            uint32_t h2, l2;
            split_pair(v, h2, l2);
            uint32_t o = swz((uint32_t)r * 128u + (uint32_t)kp * 4u);
            *(uint32_t*)((char*)sAh + o) = h2;
            *(uint32_t*)((char*)sAl + o) = l2;
        }
        __syncthreads();

#pragma unroll
        for (int ks = 0; ks < 4; ks++) {
            uint32_t kb = ks * 32;
            uint32_t ah[4], al[4];
            ldsm4(ah, aPreH + ((kb + kbA) ^ xmA));
            ldsm4(al, aPreL + ((kb + kbA) ^ xmA));
#pragma unroll
            for (int nt2 = 0; nt2 < 4; nt2++) {
                int n = nt2 * 16 + brow;
                uint32_t bo = (uint32_t)n * 128 + ((kb + kbB) ^ xmB);
                uint32_t bh4[4], bl4[4];
                ldsm4(bh4, bHb + bo);
                ldsm4(bl4, bLb + bo);
                mma16816(acc[nt2 * 2],     ah, bh4);
                mma16816(acc[nt2 * 2 + 1], ah, bh4 + 2);
                mma16816(acc[nt2 * 2],     al, bh4);
                mma16816(acc[nt2 * 2 + 1], al, bh4 + 2);
                mma16816(acc[nt2 * 2],     ah, bl4);
                mma16816(acc[nt2 * 2 + 1], ah, bl4 + 2);
            }
        }
        __syncthreads();
    }

    int r0 = v0 + wid * 16 + (lane >> 2);
    int cb = (lane & 3) * 2;
#pragma unroll
    for (int j = 0; j < 8; j++) {
        int col = j * 8 + cb;
        float bx = bias[col], by = bias[col + 1];
        float ox = tanhf(acc[j][0] + bx), oy = tanhf(acc[j][1] + by);
        float px = tanhf(acc[j][2] + bx), py = tanhf(acc[j][3] + by);
        if (outHalf) {
            if (r0 < NN)     *(__half2*)(outH + (size_t)r0 * 128 + outOff + col)       = __floats2half2_rn(ox, oy);
            if (r0 + 8 < NN) *(__half2*)(outH + (size_t)(r0 + 8) * 128 + outOff + col) = __floats2half2_rn(px, py);
        } else {
            if (r0 < NN)     *(float2*)(outF + (size_t)r0 * 128 + outOff + col)       = make_float2(ox, oy);
            if (r0 + 8 < NN) *(float2*)(outF + (size_t)(r0 + 8) * 128 + outOff + col) = make_float2(px, py);
        }
    }
}

// ---------------- fused layer-0 GEMM: stage X once, both 64-col halves; blockIdx.y = colsel ----------------
__global__ void __launch_bounds__(256) mma_gemm0_dual_k(
    const float* __restrict__ X,
    float* __restrict__ outS, __half* __restrict__ outHh)
{
    __shared__ uint32_t sAh[4096], sAl[4096];
    __shared__ uint32_t sBh[2048], sBl[2048];
    int tid = threadIdx.x, wid = tid >> 5, lane = tid & 31;
    int v0 = blockIdx.x * 128;
    int colsel = blockIdx.y;                  // 0 = left weights -> fp16 gathered, 1 = right -> fp32 self
    int bBase0 = 98304 + colsel * 32768;
    int outHalf = (colsel == 0);

    uint32_t aHb = smem_u32(sAh), aLb = smem_u32(sAl);
    uint32_t bHb = smem_u32(sBh), bLb = smem_u32(sBl);

    int lr = lane & 7, g = lane >> 3;
    int arow = wid * 16 + lr + (g & 1) * 8;
    uint32_t aPreH = aHb + arow * 128, aPreL = aLb + arow * 128;
    uint32_t xmA = (uint32_t)(arow & 7) * 16;
    uint32_t kbA = (uint32_t)(g >> 1) * 16;
    int brow = lr + (g >> 1) * 8;
    uint32_t xmB = (uint32_t)lr * 16;
    uint32_t kbB = (uint32_t)(g & 1) * 16;

    float acc[2][8][4] = {};

    for (int kc = 0; kc < 2; kc++) {
        for (int idx = tid; idx < 4096; idx += 256) {
            int r = idx >> 5, kp = idx & 31;
            float2 v = make_float2(0.f, 0.f);
            if (v0 + r < NN) v = *(const float2*)(X + (size_t)(v0 + r) * 128 + kc * 64 + kp * 2);
            uint32_t h2, l2;
            split_pair(v, h2, l2);
            uint32_t o = swz((uint32_t)r * 128u + (uint32_t)kp * 4u);
            *(uint32_t*)((char*)sAh + o) = h2;
            *(uint32_t*)((char*)sAl + o) = l2;
        }
        __syncthreads();

        for (int h = 0; h < 2; h++) {
            {
                const uint4* bh = (const uint4*)((const char*)g_WB_h + bBase0 + h * 8192 + kc * 16384);
                const uint4* bl = (const uint4*)((const char*)g_WB_l + bBase0 + h * 8192 + kc * 16384);
                for (int i = tid; i < 512; i += 256) {
                    ((uint4*)sBh)[i] = bh[i];
                    ((uint4*)sBl)[i] = bl[i];
                }
            }
            __syncthreads();
#pragma unroll
            for (int ks = 0; ks < 4; ks++) {
                uint32_t kb = ks * 32;
                uint32_t ah[4], al[4];
                ldsm4(ah, aPreH + ((kb + kbA) ^ xmA));
                ldsm4(al, aPreL + ((kb + kbA) ^ xmA));
#pragma unroll
                for (int nt2 = 0; nt2 < 4; nt2++) {
                    int n = nt2 * 16 + brow;
                    uint32_t bo = (uint32_t)n * 128 + ((kb + kbB) ^ xmB);
                    uint32_t bh4[4], bl4[4];
                    ldsm4(bh4, bHb + bo);
                    ldsm4(bl4, bLb + bo);
                    mma16816(acc[h][nt2 * 2],     ah, bh4);
                    mma16816(acc[h][nt2 * 2 + 1], ah, bh4 + 2);
                    mma16816(acc[h][nt2 * 2],     al, bh4);
                    mma16816(acc[h][nt2 * 2 + 1], al, bh4 + 2);
                    mma16816(acc[h][nt2 * 2],     ah, bl4);
                    mma16816(acc[h][nt2 * 2 + 1], ah, bl4 + 2);
                }
            }
            __syncthreads();
        }
    }

    int r0 = v0 + wid * 16 + (lane >> 2);
    int cb = (lane & 3) * 2;
#pragma unroll
    for (int h = 0; h < 2; h++) {
        int outOff = h * 64;
#pragma unroll
        for (int j = 0; j < 8; j++) {
            int col = j * 8 + cb;
            float ox = acc[h][j][0], oy = acc[h][j][1];
            float px = acc[h][j][2], py = acc[h][j][3];
            if (outHalf) {
                if (r0 < NN)     *(__half2*)(outHh + (size_t)r0 * 128 + outOff + col)       = __floats2half2_rn(ox, oy);
                if (r0 + 8 < NN) *(__half2*)(outHh + (size_t)(r0 + 8) * 128 + outOff + col) = __floats2half2_rn(px, py);
            } else {
                if (r0 < NN)     *(float2*)(outS + (size_t)r0 * 128 + outOff + col)       = make_float2(ox, oy);
                if (r0 + 8 < NN) *(float2*)(outS + (size_t)(r0 + 8) * 128 + outOff + col) = make_float2(px, py);
            }
        }
    }
}

// ---------------- Layer 0: half-warp-per-node fp16 mean-gather + self + bias + tanh ----------------
__global__ void layer0_k(const float* __restrict__ bp, const float* __restrict__ bn) {
    int v = (blockIdx.x * blockDim.x + threadIdx.x) >> 4;   // half-warp per node
    int lane = threadIdx.x & 15;
    if (v >= NN) return;
    int c4 = lane * 4;
    float4 aP = make_float4(0.f, 0.f, 0.f, 0.f);
    float4 aN = make_float4(0.f, 0.f, 0.f, 0.f);
    int b = g_rp_pos[v], e = g_rp_pos[v + 1];
#pragma unroll 4
    for (int i = b; i < e; i++) {
        int s = g_src_pos[i];
        uint2 raw = *(const uint2*)(g_U0h + (size_t)s * 128 + c4);
        float2 f0 = __half22float2(*(const __half2*)&raw.x);
        float2 f1 = __half22float2(*(const __half2*)&raw.y);
        aP.x += f0.x; aP.y += f0.y; aP.z += f1.x; aP.w += f1.y;
    }
    b = g_rp_neg[v]; e = g_rp_neg[v + 1];
#pragma unroll 4
    for (int i = b; i < e; i++) {
        int s = g_src_neg[i];
        uint2 raw = *(const uint2*)(g_U0h + (size_t)s * 128 + 64 + c4);
        float2 f0 = __half22float2(*(const __half2*)&raw.x);
        float2 f1 = __half22float2(*(const __half2*)&raw.y);
        aN.x += f0.x; aN.y += f0.y; aN.z += f1.x; aN.w += f1.y;
    }
    float ipv = g_inv_pos[v], inv = g_inv_neg[v];
    float4 sp = *(const float4*)(g_U0s + (size_t)v * 128 + c4);
    float4 sn = *(const float4*)(g_U0s + (size_t)v * 128 + 64 + c4);
    float4 b1 = *(const float4*)(bp + c4);
    float4 b2 = *(const float4*)(bn + c4);
    float4 zp, zn;
    zp.x = tanhf(aP.x * ipv + sp.x + b1.x); zp.y = tanhf(aP.y * ipv + sp.y + b1.y);
    zp.z = tanhf(aP.z * ipv + sp.z + b1.z); zp.w = tanhf(aP.w * ipv + sp.w + b1.w);
    zn.x = tanhf(aN.x * inv + sn.x + b2.x); zn.y = tanhf(aN.y * inv + sn.y + b2.y);
    zn.z = tanhf(aN.z * inv + sn.z + b2.z); zn.w = tanhf(aN.w * inv + sn.w + b2.w);
    __half2 h0 = __floats2half2_rn(zp.x, zp.y), h1 = __floats2half2_rn(zp.z, zp.w);
    __half2 h2 = __floats2half2_rn(zn.x, zn.y), h3 = __floats2half2_rn(zn.z, zn.w);
    *(uint2*)(g_Zh + (size_t)v * 128 + c4)      = make_uint2(*(uint32_t*)&h0, *(uint32_t*)&h1);
    *(uint2*)(g_Zh + (size_t)v * 128 + 64 + c4) = make_uint2(*(uint32_t*)&h2, *(uint32_t*)&h3);
}

// ---------------- Layer aggregation: half-warp-per-node fp16 gather, permuted fp32 output ----------------
__global__ void agg_k(int zsel) {
    const __half* Z = zsel ? g_Z2h : g_Zh;
    int v = (blockIdx.x * blockDim.x + threadIdx.x) >> 4;   // half-warp per node
    int lane = threadIdx.x & 15;
    if (v >= NN) return;
    int c8 = lane * 8;
    float4 aP0 = make_float4(0.f, 0.f, 0.f, 0.f), aP1 = make_float4(0.f, 0.f, 0.f, 0.f);
    float4 aN0 = make_float4(0.f, 0.f, 0.f, 0.f), aN1 = make_float4(0.f, 0.f, 0.f, 0.f);
    int b = g_rp_pos[v], e = g_rp_pos[v + 1];
#pragma unroll 4
    for (int i = b; i < e; i++) {
        int s = g_src_pos[i];
        uint4 raw = *(const uint4*)(Z + (size_t)s * 128 + c8);
        acc_h8(aP0, aP1, raw);
    }
    b = g_rp_neg[v]; e = g_rp_neg[v + 1];
#pragma unroll 4
    for (int i = b; i < e; i++) {
        int s = g_src_neg[i];
        uint4 raw = *(const uint4*)(Z + (size_t)s * 128 + c8);
        acc_h8(aN0, aN1, raw);
    }
    float ipv = g_inv_pos[v], inv = g_inv_neg[v];
    aP0.x *= ipv; aP0.y *= ipv; aP0.z *= ipv; aP0.w *= ipv;
    aP1.x *= ipv; aP1.y *= ipv; aP1.z *= ipv; aP1.w *= ipv;
    aN0.x *= inv; aN0.y *= inv; aN0.z *= inv; aN0.w *= inv;
    aN1.x *= inv; aN1.y *= inv; aN1.z *= inv; aN1.w *= inv;
    if (lane < 8) {
        // cols [0,64): Apos -> AGGP[c8], Aneg -> AGGN[64+c8]
        *(float4*)(g_AGGP + (size_t)v * 128 + c8)     = aP0;
        *(float4*)(g_AGGP + (size_t)v * 128 + c8 + 4) = aP1;
        *(float4*)(g_AGGN + (size_t)v * 128 + 64 + c8)     = aN0;
        *(float4*)(g_AGGN + (size_t)v * 128 + 64 + c8 + 4) = aN1;
    } else {
        // cols [64,128): Aneg -> AGGP[c8], Apos -> AGGN[c8-64]
        *(float4*)(g_AGGP + (size_t)v * 128 + c8)     = aN0;
        *(float4*)(g_AGGP + (size_t)v * 128 + c8 + 4) = aN1;
        *(float4*)(g_AGGN + (size_t)v * 128 + c8 - 64)     = aP0;
        *(float4*)(g_AGGN + (size_t)v * 128 + c8 - 64 + 4) = aP1;
    }
}

// ---------------- host launcher (single stream, capture-safe) ----------------
extern "C" void kernel_launch(void* const* d_in, const int* in_sizes, int n_in,
                              void* d_out, int out_size) {
    const float* x = (const float*)d_in[0];
    const int* pe = (const int*)d_in[1];   // int32 (JAX x64 disabled)
    const int* ne = (const int*)d_in[2];
    const float* bp = (const float*)d_in[5];
    const float* bn = (const float*)d_in[8];
    const float* Wp_l = (const float*)d_in[3];
    const float* Wp_r = (const float*)d_in[4];
    const float* Wn_l = (const float*)d_in[6];
    const float* Wn_r = (const float*)d_in[7];
    const float* Wl_pos = (const float*)d_in[9];
    const float* Wr_pos = (const float*)d_in[10];
    const float* b_pos = (const float*)d_in[11];
    const float* Wl_neg = (const float*)d_in[12];
    const float* Wr_neg = (const float*)d_in[13];
    const float* b_neg = (const float*)d_in[14];
    float* out = (float*)d_out;

    float *dU0s, *dAGGP, *dAGGN;
    __half *dU0h, *dZh, *dZ2h;
    cudaGetSymbolAddress((void**)&dU0h, g_U0h);
    cudaGetSymbolAddress((void**)&dU0s, g_U0s);
    cudaGetSymbolAddress((void**)&dZh, g_Zh);
    cudaGetSymbolAddress((void**)&dZ2h, g_Z2h);
    cudaGetSymbolAddress((void**)&dAGGP, g_AGGP);
    cudaGetSymbolAddress((void**)&dAGGN, g_AGGN);

    // --- weight prep ---
    prep_w_k<<<160, 256>>>(Wl_pos, Wr_pos, Wl_neg, Wr_neg, Wp_l, Wn_l, Wp_r, Wn_r);

    // --- CSR build ---
    zero_cnt_k<<<(2 * NN + 255) / 256, 256>>>();
    hist2_k<<<2048, 256>>>(pe + EE, ne + EE);
    const int NB = (NN + 1023) / 1024;
    { dim3 grd(NB, 2); scan1m_k<<<grd, 1024>>>(); }
    scan2m_k<<<2, 128>>>(NB);
    { dim3 grd((NN + 255) / 256, 2); scan3m_k<<<grd, 256>>>(); }
    scatter2_k<<<2048, 256>>>(pe, pe + EE, ne, ne + EE);

    const int NBT = (NN + 127) / 128;       // 782
    const int NBH = (NN * 16 + 255) / 256;  // 6250 (half-warp per node)

    // --- layer 0 ---
    { dim3 grd(NBT, 2); mma_gemm0_dual_k<<<grd, 256>>>(x, dU0s, dU0h); }
    layer0_k<<<NBH, 256>>>(bp, bn);

    // --- layer 1 ---
    agg_k<<<NBH, 256>>>(0);
    { dim3 grd(NBT, 2); mma_layer_dual_k<<<grd, 256>>>(dAGGP, dAGGN, dZh, 0, b_pos, b_neg, nullptr, dZ2h, 1); }

    // --- layer 2 ---
    agg_k<<<NBH, 256>>>(1);
    { dim3 grd(NBT, 2); mma_layer_dual_k<<<grd, 256>>>(dAGGP, dAGGN, dZ2h, 2 * 24576, b_pos + 64, b_neg + 64, out, nullptr, 0); }
}

// round 13
// speedup vs baseline: 1.8243x; 1.1284x over previous
#include <cuda_runtime.h>
#include <cuda_fp16.h>
#include <cstdint>

#define NN 100000
#define EE 1200000

// ---------------- device scratch (static, allocation-free) ----------------
__device__ int   g_cnt[2 * NN];
__device__ int   g_rp_pos[NN + 1];
__device__ int   g_rp_neg[NN + 1];
__device__ int   g_cur_pos[NN];
__device__ int   g_cur_neg[NN];
__device__ float g_inv_pos[NN];
__device__ float g_inv_neg[NN];
__device__ int   g_src_pos[EE];
__device__ int   g_src_neg[EE];
__device__ int   g_bsum_pos[128];
__device__ int   g_bsum_neg[128];
__device__ __align__(16) __half g_U0h[NN * 128];  // [yp(64) | yn(64)] fp16 (gathered by layer0)
__device__ float g_U0s[NN * 128];                  // [sp(64) | sn(64)] fp32 (self terms)
__device__ __align__(16) __half g_Zh[NN * 128];   // z after layer 0 (fp16)
__device__ __align__(16) __half g_Z2h[NN * 128];  // z after layer 1 (fp16)
__device__ __align__(16) __half g_AGGPh[NN * 128];  // [Apos[0:64] | Aneg[64:128]] fp16
__device__ __align__(16) __half g_AGGNh[NN * 128];  // [Apos[64:128] | Aneg[0:64]] fp16

// packed bf16 weights: 4 layer stacks (24576 B each) then gemm0 (2 x 32768 B) = 163840 B
__device__ __align__(16) uint32_t g_WB_h[40960];
__device__ __align__(16) uint32_t g_WB_l[40960];

// ---------------- helpers ----------------
__device__ __forceinline__ uint32_t smem_u32(const void* p) {
    uint32_t a;
    asm("{ .reg .u64 t; cvta.to.shared.u64 t, %1; cvt.u32.u64 %0, t; }" : "=r"(a) : "l"(p));
    return a;
}
__device__ __forceinline__ uint32_t swz(uint32_t o) { return o ^ ((o >> 3) & 0x70); }

__device__ __forceinline__ void split_pair(float2 v, uint32_t& h2, uint32_t& l2) {
    asm("cvt.rn.bf16x2.f32 %0, %1, %2;" : "=r"(h2) : "f"(v.y), "f"(v.x));
    float lx = v.x - __uint_as_float(h2 << 16);
    float ly = v.y - __uint_as_float(h2 & 0xffff0000u);
    asm("cvt.rn.bf16x2.f32 %0, %1, %2;" : "=r"(l2) : "f"(ly), "f"(lx));
}

__device__ __forceinline__ void ldsm4(uint32_t* r, uint32_t addr) {
    asm volatile("ldmatrix.sync.aligned.m8n8.x4.shared.b16 {%0,%1,%2,%3}, [%4];"
                 : "=r"(r[0]), "=r"(r[1]), "=r"(r[2]), "=r"(r[3]) : "r"(addr));
}

__device__ __forceinline__ void mma16816(float* c, const uint32_t* a, const uint32_t* b) {
    asm volatile(
        "mma.sync.aligned.m16n8k16.row.col.f32.bf16.bf16.f32 "
        "{%0,%1,%2,%3}, {%4,%5,%6,%7}, {%8,%9}, {%0,%1,%2,%3};"
        : "+f"(c[0]), "+f"(c[1]), "+f"(c[2]), "+f"(c[3])
        : "r"(a[0]), "r"(a[1]), "r"(a[2]), "r"(a[3]), "r"(b[0]), "r"(b[1]));
}

__device__ __forceinline__ void acc_h8(float4& a0, float4& a1, uint4 raw) {
    float2 f0 = __half22float2(*(const __half2*)&raw.x);
    float2 f1 = __half22float2(*(const __half2*)&raw.y);
    float2 f2 = __half22float2(*(const __half2*)&raw.z);
    float2 f3 = __half22float2(*(const __half2*)&raw.w);
    a0.x += f0.x; a0.y += f0.y; a0.z += f1.x; a0.w += f1.y;
    a1.x += f2.x; a1.y += f2.y; a1.z += f3.x; a1.w += f3.y;
}

__device__ __forceinline__ uint4 pack_h8(float4 a0, float4 a1) {
    __half2 h0 = __floats2half2_rn(a0.x, a0.y), h1 = __floats2half2_rn(a0.z, a0.w);
    __half2 h2 = __floats2half2_rn(a1.x, a1.y), h3 = __floats2half2_rn(a1.z, a1.w);
    return make_uint4(*(uint32_t*)&h0, *(uint32_t*)&h1, *(uint32_t*)&h2, *(uint32_t*)&h3);
}

// ---------------- CSR build ----------------
__global__ void zero_cnt_k() {
    int i = blockIdx.x * blockDim.x + threadIdx.x;
    if (i < 2 * NN) g_cnt[i] = 0;
}
__global__ void hist2_k(const int* __restrict__ pdst, const int* __restrict__ ndst) {
    for (int i = blockIdx.x * blockDim.x + threadIdx.x; i < 2 * EE; i += gridDim.x * blockDim.x) {
        if (i < EE) atomicAdd(&g_cnt[pdst[i]], 1);
        else        atomicAdd(&g_cnt[NN + ndst[i - EE]], 1);
    }
}
__global__ void scan1m_k() {
    int which = blockIdx.y;
    const int* cnt = g_cnt + which * NN;
    int* incl = which ? g_rp_neg : g_rp_pos;
    int* bsum = which ? g_bsum_neg : g_bsum_pos;
    __shared__ int sh[1024];
    int i = blockIdx.x * 1024 + threadIdx.x;
    int v = (i < NN) ? cnt[i] : 0;
    sh[threadIdx.x] = v;
    __syncthreads();
    for (int off = 1; off < 1024; off <<= 1) {
        int t = (threadIdx.x >= off) ? sh[threadIdx.x - off] : 0;
        __syncthreads();
        sh[threadIdx.x] += t;
        __syncthreads();
    }
    if (i < NN) incl[i] = sh[threadIdx.x];
    if (threadIdx.x == 1023) bsum[blockIdx.x] = sh[1023];
}
__global__ void scan2m_k(int nb) {
    int which = blockIdx.x;
    int* bsum = which ? g_bsum_neg : g_bsum_pos;
    __shared__ int sh[128];
    int v = (threadIdx.x < nb) ? bsum[threadIdx.x] : 0;
    sh[threadIdx.x] = v;
    __syncthreads();
    for (int off = 1; off < 128; off <<= 1) {
        int t = (threadIdx.x >= off) ? sh[threadIdx.x - off] : 0;
        __syncthreads();
        sh[threadIdx.x] += t;
        __syncthreads();
    }
    if (threadIdx.x < nb) bsum[threadIdx.x] = sh[threadIdx.x] - v;
}
__global__ void scan3m_k() {
    int which = blockIdx.y;
    const int* cnt = g_cnt + which * NN;
    int* rp = which ? g_rp_neg : g_rp_pos;
    int* cur = which ? g_cur_neg : g_cur_pos;
    float* inv = which ? g_inv_neg : g_inv_pos;
    const int* bsum = which ? g_bsum_neg : g_bsum_pos;
    int i = blockIdx.x * blockDim.x + threadIdx.x;
    if (i < NN) {
        int inc = rp[i] + bsum[i >> 10];
        int c = cnt[i];
        int ex = inc - c;
        rp[i] = ex;
        cur[i] = ex;
        inv[i] = 1.0f / (float)(c > 0 ? c : 1);
    }
    if (i == 0) rp[NN] = EE;
}
__global__ void scatter2_k(const int* __restrict__ ps, const int* __restrict__ pd,
                           const int* __restrict__ ns, const int* __restrict__ nd) {
    for (int i = blockIdx.x * blockDim.x + threadIdx.x; i < 2 * EE; i += gridDim.x * blockDim.x) {
        if (i < EE) {
            int d = pd[i];
            int p = atomicAdd(&g_cur_pos[d], 1);
            g_src_pos[p] = ps[i];
        } else {
            int d = nd[i - EE];
            int p = atomicAdd(&g_cur_neg[d], 1);
            g_src_neg[p] = ns[i - EE];
        }
    }
}

// ---------------- weight prep: fp32 -> bf16 hi/lo, [n][k] rows, SW128-swizzled 64-k chunks ----------------
__global__ void prep_w_k(const float* __restrict__ Wl_pos, const float* __restrict__ Wr_pos,
                         const float* __restrict__ Wl_neg, const float* __restrict__ Wr_neg,
                         const float* __restrict__ Wp_l, const float* __restrict__ Wn_l,
                         const float* __restrict__ Wp_r, const float* __restrict__ Wn_r) {
    int idx = blockIdx.x * blockDim.x + threadIdx.x;
    float2 v;
    uint32_t off;
    if (idx < 24576) {
        int stack = idx / 6144, rem = idx % 6144;
        int n = rem / 96, kp = rem % 96, k = kp * 2;
        int l = stack >> 1, h = stack & 1;
        const float* WL = h ? Wl_neg : Wl_pos;  // [2][128][64]
        const float* WR = h ? Wr_neg : Wr_pos;  // [2][64][64]
        if (k < 128) {
            v.x = WL[l * 8192 + k * 64 + n];
            v.y = WL[l * 8192 + (k + 1) * 64 + n];
        } else {
            int kk = k - 128;
            v.x = WR[l * 4096 + kk * 64 + n];
            v.y = WR[l * 4096 + (kk + 1) * 64 + n];
        }
        off = (uint32_t)stack * 24576u + (uint32_t)(k >> 6) * 8192u + swz((uint32_t)n * 128u + (k & 63) * 2u);
    } else if (idx < 24576 + 16384) {
        int j = idx - 24576;
        int colsel = j / 8192, rem = j % 8192;
        int n = rem / 64, kp = rem % 64, k = kp * 2;
        const float* W = (n < 64) ? (colsel ? Wp_r : Wp_l) : (colsel ? Wn_r : Wn_l);
        int nn = n & 63;
        v.x = W[k * 64 + nn];
        v.y = W[(k + 1) * 64 + nn];
        off = 98304u + (uint32_t)colsel * 32768u + (uint32_t)(k >> 6) * 16384u + swz((uint32_t)n * 128u + (k & 63) * 2u);
    } else {
        return;
    }
    uint32_t h2, l2;
    split_pair(v, h2, l2);
    g_WB_h[off >> 2] = h2;
    g_WB_l[off >> 2] = l2;
}

// ---------------- layer GEMM, both halves in one launch (blockIdx.y = half); all-fp16 A ----------------
// out_half = act([AGGh | z_half] @ [Wl;Wr] + b); chunks 0,1 from A0h (fp16), chunk 2 from A1h + zOff (fp16).
__global__ void __launch_bounds__(256) mma_layer_dual_k(
    const __half* __restrict__ A0a, const __half* __restrict__ A0b,
    const __half* __restrict__ A1h, int bBaseA,
    const float* __restrict__ biasA, const float* __restrict__ biasB,
    float* __restrict__ outF, __half* __restrict__ outH, int outHalf)
{
    __shared__ uint32_t sAh[4096], sAl[4096];
    __shared__ uint32_t sBh[2048], sBl[2048];
    int tid = threadIdx.x, wid = tid >> 5, lane = tid & 31;
    int v0 = blockIdx.x * 128;
    int h = blockIdx.y;
    const __half* A0 = h ? A0b : A0a;
    const float* bias = h ? biasB : biasA;
    int bBase = bBaseA + h * 24576;
    int zOff = h * 64, outOff = h * 64;

    uint32_t aHb = smem_u32(sAh), aLb = smem_u32(sAl);
    uint32_t bHb = smem_u32(sBh), bLb = smem_u32(sBl);

    int lr = lane & 7, g = lane >> 3;
    int arow = wid * 16 + lr + (g & 1) * 8;
    uint32_t aPreH = aHb + arow * 128, aPreL = aLb + arow * 128;
    uint32_t xmA = (uint32_t)(arow & 7) * 16;
    uint32_t kbA = (uint32_t)(g >> 1) * 16;
    int brow = lr + (g >> 1) * 8;
    uint32_t xmB = (uint32_t)lr * 16;
    uint32_t kbB = (uint32_t)(g & 1) * 16;

    float acc[8][4] = {};

    for (int kc = 0; kc < 3; kc++) {
        {
            const uint4* bh = (const uint4*)((const char*)g_WB_h + bBase + kc * 8192);
            const uint4* bl = (const uint4*)((const char*)g_WB_l + bBase + kc * 8192);
            for (int i = tid; i < 512; i += 256) {
                ((uint4*)sBh)[i] = bh[i];
                ((uint4*)sBl)[i] = bl[i];
            }
        }
        for (int idx = tid; idx < 4096; idx += 256) {
            int r = idx >> 5, kp = idx & 31;
            float2 v = make_float2(0.f, 0.f);
            if (v0 + r < NN) {
                const __half* src = (kc == 2) ? (A1h + (size_t)(v0 + r) * 128 + zOff + kp * 2)
                                              : (A0 + (size_t)(v0 + r) * 128 + kc * 64 + kp * 2);
                v = __half22float2(*(const __half2*)src);
            }
            uint32_t h2, l2;
            split_pair(v, h2, l2);
            uint32_t o = swz((uint32_t)r * 128u + (uint32_t)kp * 4u);
            *(uint32_t*)((char*)sAh + o) = h2;
            *(uint32_t*)((char*)sAl + o) = l2;
        }
        __syncthreads();

#pragma unroll
        for (int ks = 0; ks < 4; ks++) {
            uint32_t kb = ks * 32;
            uint32_t ah[4], al[4];
            ldsm4(ah, aPreH + ((kb + kbA) ^ xmA));
            ldsm4(al, aPreL + ((kb + kbA) ^ xmA));
#pragma unroll
            for (int nt2 = 0; nt2 < 4; nt2++) {
                int n = nt2 * 16 + brow;
                uint32_t bo = (uint32_t)n * 128 + ((kb + kbB) ^ xmB);
                uint32_t bh4[4], bl4[4];
                ldsm4(bh4, bHb + bo);
                ldsm4(bl4, bLb + bo);
                mma16816(acc[nt2 * 2],     ah, bh4);
                mma16816(acc[nt2 * 2 + 1], ah, bh4 + 2);
                mma16816(acc[nt2 * 2],     al, bh4);
                mma16816(acc[nt2 * 2 + 1], al, bh4 + 2);
                mma16816(acc[nt2 * 2],     ah, bl4);
                mma16816(acc[nt2 * 2 + 1], ah, bl4 + 2);
            }
        }
        __syncthreads();
    }

    int r0 = v0 + wid * 16 + (lane >> 2);
    int cb = (lane & 3) * 2;
#pragma unroll
    for (int j = 0; j < 8; j++) {
        int col = j * 8 + cb;
        float bx = bias[col], by = bias[col + 1];
        float ox = tanhf(acc[j][0] + bx), oy = tanhf(acc[j][1] + by);
        float px = tanhf(acc[j][2] + bx), py = tanhf(acc[j][3] + by);
        if (outHalf) {
            if (r0 < NN)     *(__half2*)(outH + (size_t)r0 * 128 + outOff + col)       = __floats2half2_rn(ox, oy);
            if (r0 + 8 < NN) *(__half2*)(outH + (size_t)(r0 + 8) * 128 + outOff + col) = __floats2half2_rn(px, py);
        } else {
            if (r0 < NN)     *(float2*)(outF + (size_t)r0 * 128 + outOff + col)       = make_float2(ox, oy);
            if (r0 + 8 < NN) *(float2*)(outF + (size_t)(r0 + 8) * 128 + outOff + col) = make_float2(px, py);
        }
    }
}

// ---------------- fused layer-0 GEMM: stage X once, both 64-col halves; blockIdx.y = colsel ----------------
__global__ void __launch_bounds__(256) mma_gemm0_dual_k(
    const float* __restrict__ X,
    float* __restrict__ outS, __half* __restrict__ outHh)
{
    __shared__ uint32_t sAh[4096], sAl[4096];
    __shared__ uint32_t sBh[2048], sBl[2048];
    int tid = threadIdx.x, wid = tid >> 5, lane = tid & 31;
    int v0 = blockIdx.x * 128;
    int colsel = blockIdx.y;                  // 0 = left weights -> fp16 gathered, 1 = right -> fp32 self
    int bBase0 = 98304 + colsel * 32768;
    int outHalf = (colsel == 0);

    uint32_t aHb = smem_u32(sAh), aLb = smem_u32(sAl);
    uint32_t bHb = smem_u32(sBh), bLb = smem_u32(sBl);

    int lr = lane & 7, g = lane >> 3;
    int arow = wid * 16 + lr + (g & 1) * 8;
    uint32_t aPreH = aHb + arow * 128, aPreL = aLb + arow * 128;
    uint32_t xmA = (uint32_t)(arow & 7) * 16;
    uint32_t kbA = (uint32_t)(g >> 1) * 16;
    int brow = lr + (g >> 1) * 8;
    uint32_t xmB = (uint32_t)lr * 16;
    uint32_t kbB = (uint32_t)(g & 1) * 16;

    float acc[2][8][4] = {};

    for (int kc = 0; kc < 2; kc++) {
        for (int idx = tid; idx < 4096; idx += 256) {
            int r = idx >> 5, kp = idx & 31;
            float2 v = make_float2(0.f, 0.f);
            if (v0 + r < NN) v = *(const float2*)(X + (size_t)(v0 + r) * 128 + kc * 64 + kp * 2);
            uint32_t h2, l2;
            split_pair(v, h2, l2);
            uint32_t o = swz((uint32_t)r * 128u + (uint32_t)kp * 4u);
            *(uint32_t*)((char*)sAh + o) = h2;
            *(uint32_t*)((char*)sAl + o) = l2;
        }
        __syncthreads();

        for (int h = 0; h < 2; h++) {
            {
                const uint4* bh = (const uint4*)((const char*)g_WB_h + bBase0 + h * 8192 + kc * 16384);
                const uint4* bl = (const uint4*)((const char*)g_WB_l + bBase0 + h * 8192 + kc * 16384);
                for (int i = tid; i < 512; i += 256) {
                    ((uint4*)sBh)[i] = bh[i];
                    ((uint4*)sBl)[i] = bl[i];
                }
            }
            __syncthreads();
#pragma unroll
            for (int ks = 0; ks < 4; ks++) {
                uint32_t kb = ks * 32;
                uint32_t ah[4], al[4];
                ldsm4(ah, aPreH + ((kb + kbA) ^ xmA));
                ldsm4(al, aPreL + ((kb + kbA) ^ xmA));
#pragma unroll
                for (int nt2 = 0; nt2 < 4; nt2++) {
                    int n = nt2 * 16 + brow;
                    uint32_t bo = (uint32_t)n * 128 + ((kb + kbB) ^ xmB);
                    uint32_t bh4[4], bl4[4];
                    ldsm4(bh4, bHb + bo);
                    ldsm4(bl4, bLb + bo);
                    mma16816(acc[h][nt2 * 2],     ah, bh4);
                    mma16816(acc[h][nt2 * 2 + 1], ah, bh4 + 2);
                    mma16816(acc[h][nt2 * 2],     al, bh4);
                    mma16816(acc[h][nt2 * 2 + 1], al, bh4 + 2);
                    mma16816(acc[h][nt2 * 2],     ah, bl4);
                    mma16816(acc[h][nt2 * 2 + 1], ah, bl4 + 2);
                }
            }
            __syncthreads();
        }
    }

    int r0 = v0 + wid * 16 + (lane >> 2);
    int cb = (lane & 3) * 2;
#pragma unroll
    for (int h = 0; h < 2; h++) {
        int outOff = h * 64;
#pragma unroll
        for (int j = 0; j < 8; j++) {
            int col = j * 8 + cb;
            float ox = acc[h][j][0], oy = acc[h][j][1];
            float px = acc[h][j][2], py = acc[h][j][3];
            if (outHalf) {
                if (r0 < NN)     *(__half2*)(outHh + (size_t)r0 * 128 + outOff + col)       = __floats2half2_rn(ox, oy);
                if (r0 + 8 < NN) *(__half2*)(outHh + (size_t)(r0 + 8) * 128 + outOff + col) = __floats2half2_rn(px, py);
            } else {
                if (r0 < NN)     *(float2*)(outS + (size_t)r0 * 128 + outOff + col)       = make_float2(ox, oy);
                if (r0 + 8 < NN) *(float2*)(outS + (size_t)(r0 + 8) * 128 + outOff + col) = make_float2(px, py);
            }
        }
    }
}

// ---------------- Layer 0: half-warp-per-node fp16 mean-gather + self + bias + tanh ----------------
__global__ void layer0_k(const float* __restrict__ bp, const float* __restrict__ bn) {
    int v = (blockIdx.x * blockDim.x + threadIdx.x) >> 4;   // half-warp per node
    int lane = threadIdx.x & 15;
    if (v >= NN) return;
    int c4 = lane * 4;
    float4 aP = make_float4(0.f, 0.f, 0.f, 0.f);
    float4 aN = make_float4(0.f, 0.f, 0.f, 0.f);
    int b = g_rp_pos[v], e = g_rp_pos[v + 1];
#pragma unroll 4
    for (int i = b; i < e; i++) {
        int s = g_src_pos[i];
        uint2 raw = *(const uint2*)(g_U0h + (size_t)s * 128 + c4);
        float2 f0 = __half22float2(*(const __half2*)&raw.x);
        float2 f1 = __half22float2(*(const __half2*)&raw.y);
        aP.x += f0.x; aP.y += f0.y; aP.z += f1.x; aP.w += f1.y;
    }
    b = g_rp_neg[v]; e = g_rp_neg[v + 1];
#pragma unroll 4
    for (int i = b; i < e; i++) {
        int s = g_src_neg[i];
        uint2 raw = *(const uint2*)(g_U0h + (size_t)s * 128 + 64 + c4);
        float2 f0 = __half22float2(*(const __half2*)&raw.x);
        float2 f1 = __half22float2(*(const __half2*)&raw.y);
        aN.x += f0.x; aN.y += f0.y; aN.z += f1.x; aN.w += f1.y;
    }
    float ipv = g_inv_pos[v], inv = g_inv_neg[v];
    float4 sp = *(const float4*)(g_U0s + (size_t)v * 128 + c4);
    float4 sn = *(const float4*)(g_U0s + (size_t)v * 128 + 64 + c4);
    float4 b1 = *(const float4*)(bp + c4);
    float4 b2 = *(const float4*)(bn + c4);
    float4 zp, zn;
    zp.x = tanhf(aP.x * ipv + sp.x + b1.x); zp.y = tanhf(aP.y * ipv + sp.y + b1.y);
    zp.z = tanhf(aP.z * ipv + sp.z + b1.z); zp.w = tanhf(aP.w * ipv + sp.w + b1.w);
    zn.x = tanhf(aN.x * inv + sn.x + b2.x); zn.y = tanhf(aN.y * inv + sn.y + b2.y);
    zn.z = tanhf(aN.z * inv + sn.z + b2.z); zn.w = tanhf(aN.w * inv + sn.w + b2.w);
    __half2 h0 = __floats2half2_rn(zp.x, zp.y), h1 = __floats2half2_rn(zp.z, zp.w);
    __half2 h2 = __floats2half2_rn(zn.x, zn.y), h3 = __floats2half2_rn(zn.z, zn.w);
    *(uint2*)(g_Zh + (size_t)v * 128 + c4)      = make_uint2(*(uint32_t*)&h0, *(uint32_t*)&h1);
    *(uint2*)(g_Zh + (size_t)v * 128 + 64 + c4) = make_uint2(*(uint32_t*)&h2, *(uint32_t*)&h3);
}

// ---------------- Layer aggregation: half-warp-per-node fp16 gather, permuted fp16 output ----------------
__global__ void agg_k(int zsel) {
    const __half* Z = zsel ? g_Z2h : g_Zh;
    int v = (blockIdx.x * blockDim.x + threadIdx.x) >> 4;   // half-warp per node
    int lane = threadIdx.x & 15;
    if (v >= NN) return;
    int c8 = lane * 8;
    float4 aP0 = make_float4(0.f, 0.f, 0.f, 0.f), aP1 = make_float4(0.f, 0.f, 0.f, 0.f);
    float4 aN0 = make_float4(0.f, 0.f, 0.f, 0.f), aN1 = make_float4(0.f, 0.f, 0.f, 0.f);
    int b = g_rp_pos[v], e = g_rp_pos[v + 1];
#pragma unroll 4
    for (int i = b; i < e; i++) {
        int s = g_src_pos[i];
        uint4 raw = *(const uint4*)(Z + (size_t)s * 128 + c8);
        acc_h8(aP0, aP1, raw);
    }
    b = g_rp_neg[v]; e = g_rp_neg[v + 1];
#pragma unroll 4
    for (int i = b; i < e; i++) {
        int s = g_src_neg[i];
        uint4 raw = *(const uint4*)(Z + (size_t)s * 128 + c8);
        acc_h8(aN0, aN1, raw);
    }
    float ipv = g_inv_pos[v], inv = g_inv_neg[v];
    aP0.x *= ipv; aP0.y *= ipv; aP0.z *= ipv; aP0.w *= ipv;
    aP1.x *= ipv; aP1.y *= ipv; aP1.z *= ipv; aP1.w *= ipv;
    aN0.x *= inv; aN0.y *= inv; aN0.z *= inv; aN0.w *= inv;
    aN1.x *= inv; aN1.y *= inv; aN1.z *= inv; aN1.w *= inv;
    uint4 pP = pack_h8(aP0, aP1);
    uint4 pN = pack_h8(aN0, aN1);
    if (lane < 8) {
        // cols [0,64): Apos -> AGGP[c8], Aneg -> AGGN[64+c8]
        *(uint4*)(g_AGGPh + (size_t)v * 128 + c8)      = pP;
        *(uint4*)(g_AGGNh + (size_t)v * 128 + 64 + c8) = pN;
    } else {
        // cols [64,128): Aneg -> AGGP[c8], Apos -> AGGN[c8-64]
        *(uint4*)(g_AGGPh + (size_t)v * 128 + c8)      = pN;
        *(uint4*)(g_AGGNh + (size_t)v * 128 + c8 - 64) = pP;
    }
}

// ---------------- host launcher (single stream, capture-safe) ----------------
extern "C" void kernel_launch(void* const* d_in, const int* in_sizes, int n_in,
                              void* d_out, int out_size) {
    const float* x = (const float*)d_in[0];
    const int* pe = (const int*)d_in[1];   // int32 (JAX x64 disabled)
    const int* ne = (const int*)d_in[2];
    const float* Wp_l = (const float*)d_in[3];
    const float* Wp_r = (const float*)d_in[4];
    const float* bp = (const float*)d_in[5];
    const float* Wn_l = (const float*)d_in[6];
    const float* Wn_r = (const float*)d_in[7];
    const float* bn = (const float*)d_in[8];
    const float* Wl_pos = (const float*)d_in[9];
    const float* Wr_pos = (const float*)d_in[10];
    const float* b_pos = (const float*)d_in[11];
    const float* Wl_neg = (const float*)d_in[12];
    const float* Wr_neg = (const float*)d_in[13];
    const float* b_neg = (const float*)d_in[14];
    float* out = (float*)d_out;

    float *dU0s;
    __half *dU0h, *dZh, *dZ2h, *dAGGPh, *dAGGNh;
    cudaGetSymbolAddress((void**)&dU0h, g_U0h);
    cudaGetSymbolAddress((void**)&dU0s, g_U0s);
    cudaGetSymbolAddress((void**)&dZh, g_Zh);
    cudaGetSymbolAddress((void**)&dZ2h, g_Z2h);
    cudaGetSymbolAddress((void**)&dAGGPh, g_AGGPh);
    cudaGetSymbolAddress((void**)&dAGGNh, g_AGGNh);

    // --- weight prep ---
    prep_w_k<<<160, 256>>>(Wl_pos, Wr_pos, Wl_neg, Wr_neg, Wp_l, Wn_l, Wp_r, Wn_r);

    // --- CSR build ---
    zero_cnt_k<<<(2 * NN + 255) / 256, 256>>>();
    hist2_k<<<2048, 256>>>(pe + EE, ne + EE);
    const int NB = (NN + 1023) / 1024;
    { dim3 grd(NB, 2); scan1m_k<<<grd, 1024>>>(); }
    scan2m_k<<<2, 128>>>(NB);
    { dim3 grd((NN + 255) / 256, 2); scan3m_k<<<grd, 256>>>(); }
    scatter2_k<<<2048, 256>>>(pe, pe + EE, ne, ne + EE);

    const int NBT = (NN + 127) / 128;       // 782
    const int NBH = (NN * 16 + 255) / 256;  // 6250 (half-warp per node)

    // --- layer 0 ---
    { dim3 grd(NBT, 2); mma_gemm0_dual_k<<<grd, 256>>>(x, dU0s, dU0h); }
    layer0_k<<<NBH, 256>>>(bp, bn);

    // --- layer 1 ---
    agg_k<<<NBH, 256>>>(0);
    { dim3 grd(NBT, 2); mma_layer_dual_k<<<grd, 256>>>(dAGGPh, dAGGNh, dZh, 0, b_pos, b_neg, nullptr, dZ2h, 1); }

    // --- layer 2 ---
    agg_k<<<NBH, 256>>>(1);
    { dim3 grd(NBT, 2); mma_layer_dual_k<<<grd, 256>>>(dAGGPh, dAGGNh, dZ2h, 2 * 24576, b_pos + 64, b_neg + 64, out, nullptr, 0); }
}